// round 2
// baseline (speedup 1.0000x reference)
#include <cuda_runtime.h>
#include <math.h>

#define BSZ 2
#define SEQ 2048
#define DMODEL 1024
#define NH 16
#define HD 64
#define MROWS (BSZ * SEQ)   // 4096

// -------- scratch (device globals; no allocation allowed) --------
__device__ float g_Q[BSZ * SEQ * DMODEL];
__device__ float g_K[BSZ * SEQ * DMODEL];
__device__ float g_V[BSZ * SEQ * DMODEL];
__device__ float g_C[BSZ * SEQ * DMODEL];

// ============================================================================
// Tiled SGEMM with bias: C[M,N] = A[M,K] @ W[K,N] + b[N]
// M=4096, N=K=1024 fixed. BM=BN=128, BK=8, 256 threads, 8x8 per-thread tile.
// phase 0: A=X, z in {0,1,2} selects (Wq,bq)->g_Q, (Wk,bk)->g_K, (Wv,bv)->g_V
// phase 1: A=g_C, (W0,b0)=(Wo,bo) -> Out (d_out)
// ============================================================================
__global__ __launch_bounds__(256) void sgemm_bias(
    const float* __restrict__ Xin,
    const float* __restrict__ W0, const float* __restrict__ b0,
    const float* __restrict__ W1, const float* __restrict__ b1,
    const float* __restrict__ W2, const float* __restrict__ b2,
    float* __restrict__ Out, int phase)
{
    constexpr int N = DMODEL;
    constexpr int K = DMODEL;

    const float* A;
    const float* W;
    const float* bias;
    float* C;
    if (phase == 0) {
        int z = blockIdx.z;
        A = Xin;
        W    = (z == 0) ? W0 : (z == 1) ? W1 : W2;
        bias = (z == 0) ? b0 : (z == 1) ? b1 : b2;
        C    = (z == 0) ? g_Q : (z == 1) ? g_K : g_V;
    } else {
        A = g_C; W = W0; bias = b0; C = Out;
    }

    __shared__ float As[8][128];   // transposed A tile: As[k][m]
    __shared__ float Ws[8][128];   // W tile: Ws[k][n]

    const int t  = threadIdx.x;
    const int tx = t & 15;         // 0..15 -> output cols tx*8
    const int ty = t >> 4;         // 0..15 -> output rows ty*8
    const int bm = blockIdx.y * 128;
    const int bn = blockIdx.x * 128;

    const int arow  = t >> 1;          // 0..127
    const int acol4 = (t & 1) * 4;     // 0 or 4
    const int wrow  = t >> 5;          // 0..7
    const int wcol4 = (t & 31) * 4;    // 0..124

    float acc[8][8];
#pragma unroll
    for (int i = 0; i < 8; i++)
#pragma unroll
        for (int j = 0; j < 8; j++) acc[i][j] = 0.0f;

    for (int k0 = 0; k0 < K; k0 += 8) {
        float4 av = *(const float4*)&A[(size_t)(bm + arow) * K + k0 + acol4];
        float4 wv = *(const float4*)&W[(size_t)(k0 + wrow) * N + bn + wcol4];
        As[acol4 + 0][arow] = av.x;
        As[acol4 + 1][arow] = av.y;
        As[acol4 + 2][arow] = av.z;
        As[acol4 + 3][arow] = av.w;
        *(float4*)&Ws[wrow][wcol4] = wv;
        __syncthreads();

#pragma unroll
        for (int k = 0; k < 8; k++) {
            float af[8], wf[8];
            *(float4*)&af[0] = *(const float4*)&As[k][ty * 8 + 0];
            *(float4*)&af[4] = *(const float4*)&As[k][ty * 8 + 4];
            *(float4*)&wf[0] = *(const float4*)&Ws[k][tx * 8 + 0];
            *(float4*)&wf[4] = *(const float4*)&Ws[k][tx * 8 + 4];
#pragma unroll
            for (int i = 0; i < 8; i++)
#pragma unroll
                for (int j = 0; j < 8; j++) acc[i][j] += af[i] * wf[j];
        }
        __syncthreads();
    }

    // epilogue: add bias, write out
    float bfr[8];
    *(float4*)&bfr[0] = *(const float4*)&bias[bn + tx * 8 + 0];
    *(float4*)&bfr[4] = *(const float4*)&bias[bn + tx * 8 + 4];
#pragma unroll
    for (int i = 0; i < 8; i++) {
        const size_t row = (size_t)(bm + ty * 8 + i);
        float4 o0 = make_float4(acc[i][0] + bfr[0], acc[i][1] + bfr[1],
                                acc[i][2] + bfr[2], acc[i][3] + bfr[3]);
        float4 o1 = make_float4(acc[i][4] + bfr[4], acc[i][5] + bfr[5],
                                acc[i][6] + bfr[6], acc[i][7] + bfr[7]);
        *(float4*)&C[row * N + bn + tx * 8 + 0] = o0;
        *(float4*)&C[row * N + bn + tx * 8 + 4] = o1;
    }
}

// ============================================================================
// Flash attention: per (b,h), BR=64 query rows per block, BC=32 key cols/tile.
// Online softmax, O accumulators in registers (4 rows x 4 cols per thread).
// ============================================================================
#define BR 64
#define BC 32

__global__ __launch_bounds__(256) void attn_kernel(const float* __restrict__ mask)
{
    __shared__ float Qs[BR][HD + 4];      // q(r,d)
    __shared__ float Kts[HD][BC + 4];     // k(c,d) stored transposed: Kts[d][c]
    __shared__ float Vs[BC][HD + 4];      // v(c,d)
    __shared__ float Ps[BR][BC + 4];      // scores then probabilities
    __shared__ float m_s[BR], l_s[BR], alpha_s[BR];
    __shared__ float colpen[BC];

    const int t  = threadIdx.x;
    const int bh = blockIdx.y;
    const int b  = bh / NH;
    const int h  = bh % NH;
    const int q0 = blockIdx.x * BR;

    const float* Qg = g_Q + (size_t)b * SEQ * DMODEL + h * HD;
    const float* Kg = g_K + (size_t)b * SEQ * DMODEL + h * HD;
    const float* Vg = g_V + (size_t)b * SEQ * DMODEL + h * HD;

    // load Q tile [BR x HD]
    for (int i = t; i < BR * HD / 4; i += 256) {
        int r  = i >> 4;             // HD/4 = 16
        int d4 = (i & 15) * 4;
        *(float4*)&Qs[r][d4] = *(const float4*)&Qg[(size_t)(q0 + r) * DMODEL + d4];
    }
    if (t < BR) { m_s[t] = -1e30f; l_s[t] = 0.0f; }

    // phase-A mapping: 4 rows x 2 cols per thread
    const int acx = t & 15;          // cols 2*acx, 2*acx+1
    const int ary = t >> 4;          // rows 4*ary .. 4*ary+3
    // phase-C mapping: 4 rows x 4 d-cols per thread
    const int cdx = t & 15;          // d cols 4*cdx..+3
    const int cry = t >> 4;          // rows 4*cry..+3

    float o[4][4];
#pragma unroll
    for (int i = 0; i < 4; i++)
#pragma unroll
        for (int j = 0; j < 4; j++) o[i][j] = 0.0f;

    for (int kb = 0; kb < SEQ / BC; kb++) {
        const int c0 = kb * BC;
        // load K tile transposed, V tile direct
        for (int i = t; i < BC * HD / 4; i += 256) {
            int c  = i >> 4;
            int d4 = (i & 15) * 4;
            float4 kv = *(const float4*)&Kg[(size_t)(c0 + c) * DMODEL + d4];
            Kts[d4 + 0][c] = kv.x;
            Kts[d4 + 1][c] = kv.y;
            Kts[d4 + 2][c] = kv.z;
            Kts[d4 + 3][c] = kv.w;
            *(float4*)&Vs[c][d4] = *(const float4*)&Vg[(size_t)(c0 + c) * DMODEL + d4];
        }
        if (t < BC) colpen[t] = -1e6f * (1.0f - mask[b * SEQ + c0 + t]);
        __syncthreads();

        // ---- phase A: S = (Q @ K^T) * scale + colpen ----
        {
            float s0[4], s1[4];
#pragma unroll
            for (int i = 0; i < 4; i++) { s0[i] = 0.0f; s1[i] = 0.0f; }
#pragma unroll
            for (int d = 0; d < HD; d += 2) {
                float2 kA = *(const float2*)&Kts[d + 0][2 * acx];
                float2 kB = *(const float2*)&Kts[d + 1][2 * acx];
#pragma unroll
                for (int i = 0; i < 4; i++) {
                    float2 q = *(const float2*)&Qs[4 * ary + i][d];
                    s0[i] += q.x * kA.x + q.y * kB.x;
                    s1[i] += q.x * kA.y + q.y * kB.y;
                }
            }
            const float scale = 0.125f; // 1/sqrt(64)
            float p0 = colpen[2 * acx], p1 = colpen[2 * acx + 1];
#pragma unroll
            for (int i = 0; i < 4; i++) {
                Ps[4 * ary + i][2 * acx + 0] = s0[i] * scale + p0;
                Ps[4 * ary + i][2 * acx + 1] = s1[i] * scale + p1;
            }
        }
        __syncthreads();

        // ---- phase B: online softmax (4 threads per row, 8 cols each) ----
        {
            const int r   = t >> 2;
            const int sub = t & 3;
            float mx = -1e30f;
#pragma unroll
            for (int j = 0; j < 8; j++) mx = fmaxf(mx, Ps[r][sub * 8 + j]);
            mx = fmaxf(mx, __shfl_xor_sync(0xffffffffu, mx, 1));
            mx = fmaxf(mx, __shfl_xor_sync(0xffffffffu, mx, 2));
            const float mold = m_s[r];
            const float mnew = fmaxf(mold, mx);
            float sum = 0.0f;
#pragma unroll
            for (int j = 0; j < 8; j++) {
                float p = __expf(Ps[r][sub * 8 + j] - mnew);
                Ps[r][sub * 8 + j] = p;
                sum += p;
            }
            sum += __shfl_xor_sync(0xffffffffu, sum, 1);
            sum += __shfl_xor_sync(0xffffffffu, sum, 2);
            if (sub == 0) {
                float al = __expf(mold - mnew);
                alpha_s[r] = al;
                l_s[r] = l_s[r] * al + sum;
                m_s[r] = mnew;
            }
        }
        __syncthreads();

        // ---- phase C: O = O*alpha + P @ V ----
        {
            float al[4];
#pragma unroll
            for (int i = 0; i < 4; i++) al[i] = alpha_s[4 * cry + i];
#pragma unroll
            for (int i = 0; i < 4; i++)
#pragma unroll
                for (int j = 0; j < 4; j++) o[i][j] *= al[i];

#pragma unroll
            for (int c = 0; c < BC; c += 2) {
                float4 vA = *(const float4*)&Vs[c + 0][4 * cdx];
                float4 vB = *(const float4*)&Vs[c + 1][4 * cdx];
#pragma unroll
                for (int i = 0; i < 4; i++) {
                    float2 p = *(const float2*)&Ps[4 * cry + i][c];
                    o[i][0] += p.x * vA.x + p.y * vB.x;
                    o[i][1] += p.x * vA.y + p.y * vB.y;
                    o[i][2] += p.x * vA.z + p.y * vB.z;
                    o[i][3] += p.x * vA.w + p.y * vB.w;
                }
            }
        }
        __syncthreads();
    }

    // write ctx = O / l
#pragma unroll
    for (int i = 0; i < 4; i++) {
        const int r = 4 * cry + i;
        const float inv = 1.0f / l_s[r];
        const size_t row = (size_t)(b * SEQ + q0 + r);
        float4 v = make_float4(o[i][0] * inv, o[i][1] * inv, o[i][2] * inv, o[i][3] * inv);
        *(float4*)&g_C[row * DMODEL + h * HD + 4 * cdx] = v;
    }
}

// ============================================================================
extern "C" void kernel_launch(void* const* d_in, const int* in_sizes, int n_in,
                              void* d_out, int out_size)
{
    const float* X    = (const float*)d_in[0];
    const float* mask = (const float*)d_in[1];
    const float* Wq   = (const float*)d_in[2];
    const float* bq   = (const float*)d_in[3];
    const float* Wk   = (const float*)d_in[4];
    const float* bk   = (const float*)d_in[5];
    const float* Wv   = (const float*)d_in[6];
    const float* bv   = (const float*)d_in[7];
    const float* Wo   = (const float*)d_in[8];
    const float* bo   = (const float*)d_in[9];
    float* out = (float*)d_out;

    dim3 blk(256);
    dim3 gqkv(DMODEL / 128, MROWS / 128, 3);   // 8 x 32 x 3
    dim3 gout(DMODEL / 128, MROWS / 128, 1);
    dim3 gattn(SEQ / BR, BSZ * NH);            // 32 x 32

    // QKV projections (fused launch, z selects which)
    sgemm_bias<<<gqkv, blk>>>(X, Wq, bq, Wk, bk, Wv, bv, nullptr, 0);
    // flash attention
    attn_kernel<<<gattn, blk>>>(mask);
    // output projection -> d_out
    sgemm_bias<<<gout, blk>>>(nullptr, Wo, bo, nullptr, nullptr, nullptr, nullptr, out, 1);
}

// round 5
// speedup vs baseline: 1.4807x; 1.4807x over previous
#include <cuda_runtime.h>
#include <math.h>
#include <stdint.h>

#define BSZ 2
#define SEQ 2048
#define DMODEL 1024
#define NH 16
#define HD 64
#define MROWS (BSZ * SEQ)   // 4096
#define NQKV (3 * DMODEL)   // 3072

// -------- scratch (device globals; no allocation allowed) --------
__device__ float g_A[MROWS * DMODEL];        // tf32-rounded X
__device__ float g_QKV[MROWS * NQKV];        // fused Q|K|V, row stride 3072
__device__ float g_C[MROWS * DMODEL];        // attention output (tf32-rounded)
__device__ float g_WtQKV[NQKV * DMODEL];     // transposed+rounded Wq|Wk|Wv  [n][k]
__device__ float g_WtO[DMODEL * DMODEL];     // transposed+rounded Wo        [n][k]
__device__ float g_biasQKV[NQKV];

__device__ __forceinline__ float rna_tf32(float x) {
    uint32_t u;
    asm("cvt.rna.tf32.f32 %0, %1;" : "=r"(u) : "f"(x));
    return __uint_as_float(u);
}

// ============================================================================
// tf32 mma.sync GEMM: C[M, Ntot] = A[M,1024] @ Bt[Ntot,1024]^T + bias
// CTA tile 128x128, BK=32, 256 threads = 8 warps (2 m x 4 n), warp tile 64x32.
// Smem rows padded to stride 36 floats: conflict-free frag LDS + aligned STS.128.
// ============================================================================
#define BK 32
#define SM_STRIDE 36
#define SM_ATILE (128 * SM_STRIDE)          // 4608 floats
#define SM_STAGE (2 * SM_ATILE)             // A + B = 9216 floats
#define GEMM_SMEM (2 * SM_STAGE * 4)        // 73728 bytes

__device__ __forceinline__ void mma_tf32(float& c0, float& c1, float& c2, float& c3,
                                         uint32_t a0, uint32_t a1, uint32_t a2, uint32_t a3,
                                         uint32_t b0, uint32_t b1) {
    asm volatile(
        "mma.sync.aligned.m16n8k8.row.col.f32.tf32.tf32.f32 "
        "{%0,%1,%2,%3}, {%4,%5,%6,%7}, {%8,%9}, {%0,%1,%2,%3};"
        : "+f"(c0), "+f"(c1), "+f"(c2), "+f"(c3)
        : "r"(a0), "r"(a1), "r"(a2), "r"(a3), "r"(b0), "r"(b1));
}

__global__ __launch_bounds__(256) void gemm_mma(
    const float* __restrict__ A, const float* __restrict__ Bt,
    const float* __restrict__ bias, float* __restrict__ C, int Ntot)
{
    extern __shared__ float sm[];
    const int t    = threadIdx.x;
    const int wid  = t >> 5;
    const int lane = t & 31;
    const int wm   = wid >> 2;     // 0..1
    const int wn   = wid & 3;      // 0..3
    const int lrow = lane >> 2;    // 0..7
    const int lcol = lane & 3;     // 0..3
    const int bm = blockIdx.y * 128;
    const int bn = blockIdx.x * 128;

    const float* Ag = A  + (size_t)bm * DMODEL;
    const float* Bg = Bt + (size_t)bn * DMODEL;

    float acc[4][4][4];
#pragma unroll
    for (int mt = 0; mt < 4; mt++)
#pragma unroll
        for (int nt = 0; nt < 4; nt++)
#pragma unroll
            for (int r = 0; r < 4; r++) acc[mt][nt][r] = 0.0f;

    // per-thread load mapping: j in 0..3, lin = t + j*256 (0..1023)
    //   row = lin>>3 (0..127), k4 = (lin&7)*4
    int lrw[4], lk4[4];
#pragma unroll
    for (int j = 0; j < 4; j++) {
        int lin = t + j * 256;
        lrw[j] = lin >> 3;
        lk4[j] = (lin & 7) * 4;
    }

    float4 ra[4], rb[4];

    // prologue: load iter 0
#pragma unroll
    for (int j = 0; j < 4; j++) {
        ra[j] = *(const float4*)&Ag[(size_t)lrw[j] * DMODEL + lk4[j]];
        rb[j] = *(const float4*)&Bg[(size_t)lrw[j] * DMODEL + lk4[j]];
    }
#pragma unroll
    for (int j = 0; j < 4; j++) {
        *(float4*)&sm[lrw[j] * SM_STRIDE + lk4[j]] = ra[j];
        *(float4*)&sm[SM_ATILE + lrw[j] * SM_STRIDE + lk4[j]] = rb[j];
    }
    __syncthreads();

    const int NITER = DMODEL / BK;    // 32
    for (int it = 0; it < NITER; it++) {
        const int cur = it & 1;
        // prefetch next K-slab while computing
        if (it + 1 < NITER) {
            const int kb = (it + 1) * BK;
#pragma unroll
            for (int j = 0; j < 4; j++) {
                ra[j] = *(const float4*)&Ag[(size_t)lrw[j] * DMODEL + kb + lk4[j]];
                rb[j] = *(const float4*)&Bg[(size_t)lrw[j] * DMODEL + kb + lk4[j]];
            }
        }

        const float* sa = sm + cur * SM_STAGE;
        const float* sb = sa + SM_ATILE;
#pragma unroll
        for (int ks = 0; ks < 4; ks++) {
            const int k0 = ks * 8 + lcol;
            uint32_t af[4][4];
#pragma unroll
            for (int mt = 0; mt < 4; mt++) {
                const int r0 = (wm * 64 + mt * 16 + lrow) * SM_STRIDE;
                af[mt][0] = __float_as_uint(sa[r0 + k0]);
                af[mt][1] = __float_as_uint(sa[r0 + 8 * SM_STRIDE + k0]);
                af[mt][2] = __float_as_uint(sa[r0 + k0 + 4]);
                af[mt][3] = __float_as_uint(sa[r0 + 8 * SM_STRIDE + k0 + 4]);
            }
#pragma unroll
            for (int nt = 0; nt < 4; nt++) {
                const int n0 = (wn * 32 + nt * 8 + lrow) * SM_STRIDE;
                uint32_t b0 = __float_as_uint(sb[n0 + k0]);
                uint32_t b1 = __float_as_uint(sb[n0 + k0 + 4]);
#pragma unroll
                for (int mt = 0; mt < 4; mt++)
                    mma_tf32(acc[mt][nt][0], acc[mt][nt][1], acc[mt][nt][2], acc[mt][nt][3],
                             af[mt][0], af[mt][1], af[mt][2], af[mt][3], b0, b1);
            }
        }

        if (it + 1 < NITER) {
            float* da = sm + (cur ^ 1) * SM_STAGE;
#pragma unroll
            for (int j = 0; j < 4; j++) {
                *(float4*)&da[lrw[j] * SM_STRIDE + lk4[j]] = ra[j];
                *(float4*)&da[SM_ATILE + lrw[j] * SM_STRIDE + lk4[j]] = rb[j];
            }
        }
        __syncthreads();
    }

    // epilogue: add bias, write (32B-sector-aligned float2 stores)
#pragma unroll
    for (int mt = 0; mt < 4; mt++) {
#pragma unroll
        for (int nt = 0; nt < 4; nt++) {
            const int row = bm + wm * 64 + mt * 16 + lrow;
            const int col = bn + wn * 32 + nt * 8 + lcol * 2;
            const float bz0 = __ldg(&bias[col]);
            const float bz1 = __ldg(&bias[col + 1]);
            float2 v0 = make_float2(acc[mt][nt][0] + bz0, acc[mt][nt][1] + bz1);
            float2 v1 = make_float2(acc[mt][nt][2] + bz0, acc[mt][nt][3] + bz1);
            *(float2*)&C[(size_t)row * Ntot + col] = v0;
            *(float2*)&C[(size_t)(row + 8) * Ntot + col] = v1;
        }
    }
}

// ============================================================================
// prep kernels
// ============================================================================
__global__ void prep_round_X(const float* __restrict__ X, float* __restrict__ out) {
    int i = blockIdx.x * blockDim.x + threadIdx.x;
    if (i < MROWS * DMODEL) out[i] = rna_tf32(X[i]);
}

__global__ void prep_transpose(const float* __restrict__ Wq, const float* __restrict__ Wk,
                               const float* __restrict__ Wv, const float* __restrict__ Wo) {
    __shared__ float tile[32][33];
    const int z = blockIdx.z;
    const float* W = (z == 0) ? Wq : (z == 1) ? Wk : (z == 2) ? Wv : Wo;
    float* Dst = (z == 3) ? g_WtO : (g_WtQKV + (size_t)z * DMODEL * DMODEL);
    const int n0 = blockIdx.x * 32, k0 = blockIdx.y * 32;
    const int tx = threadIdx.x, ty0 = threadIdx.y;
#pragma unroll
    for (int ty = ty0; ty < 32; ty += 8)
        tile[ty][tx] = rna_tf32(W[(size_t)(k0 + ty) * DMODEL + n0 + tx]);
    __syncthreads();
#pragma unroll
    for (int ty = ty0; ty < 32; ty += 8)
        Dst[(size_t)(n0 + ty) * DMODEL + k0 + tx] = tile[tx][ty];
}

__global__ void prep_bias(const float* __restrict__ bq, const float* __restrict__ bk,
                          const float* __restrict__ bv) {
    int i = blockIdx.x * blockDim.x + threadIdx.x;
    if (i < NQKV)
        g_biasQKV[i] = (i < 1024) ? bq[i] : (i < 2048) ? bk[i - 1024] : bv[i - 2048];
}

// ============================================================================
// Flash attention (unchanged; fused-QKV addressing, tf32-rounded output)
// ============================================================================
#define BR 64
#define BC 32

__global__ __launch_bounds__(256) void attn_kernel(const float* __restrict__ mask)
{
    __shared__ float Qs[BR][HD + 4];
    __shared__ float Kts[HD][BC + 4];
    __shared__ float Vs[BC][HD + 4];
    __shared__ float Ps[BR][BC + 4];
    __shared__ float m_s[BR], l_s[BR], alpha_s[BR];
    __shared__ float colpen[BC];

    const int t  = threadIdx.x;
    const int bh = blockIdx.y;
    const int b  = bh / NH;
    const int h  = bh % NH;
    const int q0 = blockIdx.x * BR;

    const float* Qg = g_QKV + (size_t)b * SEQ * NQKV + 0 * DMODEL + h * HD;
    const float* Kg = g_QKV + (size_t)b * SEQ * NQKV + 1 * DMODEL + h * HD;
    const float* Vg = g_QKV + (size_t)b * SEQ * NQKV + 2 * DMODEL + h * HD;

    for (int i = t; i < BR * HD / 4; i += 256) {
        int r  = i >> 4;
        int d4 = (i & 15) * 4;
        *(float4*)&Qs[r][d4] = *(const float4*)&Qg[(size_t)(q0 + r) * NQKV + d4];
    }
    if (t < BR) { m_s[t] = -1e30f; l_s[t] = 0.0f; }

    const int acx = t & 15;
    const int ary = t >> 4;
    const int cdx = t & 15;
    const int cry = t >> 4;

    float o[4][4];
#pragma unroll
    for (int i = 0; i < 4; i++)
#pragma unroll
        for (int j = 0; j < 4; j++) o[i][j] = 0.0f;

    for (int kb = 0; kb < SEQ / BC; kb++) {
        const int c0 = kb * BC;
        for (int i = t; i < BC * HD / 4; i += 256) {
            int c  = i >> 4;
            int d4 = (i & 15) * 4;
            float4 kv = *(const float4*)&Kg[(size_t)(c0 + c) * NQKV + d4];
            Kts[d4 + 0][c] = kv.x;
            Kts[d4 + 1][c] = kv.y;
            Kts[d4 + 2][c] = kv.z;
            Kts[d4 + 3][c] = kv.w;
            *(float4*)&Vs[c][d4] = *(const float4*)&Vg[(size_t)(c0 + c) * NQKV + d4];
        }
        if (t < BC) colpen[t] = -1e6f * (1.0f - mask[b * SEQ + c0 + t]);
        __syncthreads();

        {
            float s0[4], s1[4];
#pragma unroll
            for (int i = 0; i < 4; i++) { s0[i] = 0.0f; s1[i] = 0.0f; }
#pragma unroll
            for (int d = 0; d < HD; d += 2) {
                float2 kA = *(const float2*)&Kts[d + 0][2 * acx];
                float2 kB = *(const float2*)&Kts[d + 1][2 * acx];
#pragma unroll
                for (int i = 0; i < 4; i++) {
                    float2 q = *(const float2*)&Qs[4 * ary + i][d];
                    s0[i] += q.x * kA.x + q.y * kB.x;
                    s1[i] += q.x * kA.y + q.y * kB.y;
                }
            }
            const float scale = 0.125f;
            float p0 = colpen[2 * acx], p1 = colpen[2 * acx + 1];
#pragma unroll
            for (int i = 0; i < 4; i++) {
                Ps[4 * ary + i][2 * acx + 0] = s0[i] * scale + p0;
                Ps[4 * ary + i][2 * acx + 1] = s1[i] * scale + p1;
            }
        }
        __syncthreads();

        {
            const int r   = t >> 2;
            const int sub = t & 3;
            float mx = -1e30f;
#pragma unroll
            for (int j = 0; j < 8; j++) mx = fmaxf(mx, Ps[r][sub * 8 + j]);
            mx = fmaxf(mx, __shfl_xor_sync(0xffffffffu, mx, 1));
            mx = fmaxf(mx, __shfl_xor_sync(0xffffffffu, mx, 2));
            const float mold = m_s[r];
            const float mnew = fmaxf(mold, mx);
            float sum = 0.0f;
#pragma unroll
            for (int j = 0; j < 8; j++) {
                float p = __expf(Ps[r][sub * 8 + j] - mnew);
                Ps[r][sub * 8 + j] = p;
                sum += p;
            }
            sum += __shfl_xor_sync(0xffffffffu, sum, 1);
            sum += __shfl_xor_sync(0xffffffffu, sum, 2);
            if (sub == 0) {
                float al = __expf(mold - mnew);
                alpha_s[r] = al;
                l_s[r] = l_s[r] * al + sum;
                m_s[r] = mnew;
            }
        }
        __syncthreads();

        {
            float al[4];
#pragma unroll
            for (int i = 0; i < 4; i++) al[i] = alpha_s[4 * cry + i];
#pragma unroll
            for (int i = 0; i < 4; i++)
#pragma unroll
                for (int j = 0; j < 4; j++) o[i][j] *= al[i];

#pragma unroll
            for (int c = 0; c < BC; c += 2) {
                float4 vA = *(const float4*)&Vs[c + 0][4 * cdx];
                float4 vB = *(const float4*)&Vs[c + 1][4 * cdx];
#pragma unroll
                for (int i = 0; i < 4; i++) {
                    float2 p = *(const float2*)&Ps[4 * cry + i][c];
                    o[i][0] += p.x * vA.x + p.y * vB.x;
                    o[i][1] += p.x * vA.y + p.y * vB.y;
                    o[i][2] += p.x * vA.z + p.y * vB.z;
                    o[i][3] += p.x * vA.w + p.y * vB.w;
                }
            }
        }
        __syncthreads();
    }

#pragma unroll
    for (int i = 0; i < 4; i++) {
        const int r = 4 * cry + i;
        const float inv = 1.0f / l_s[r];
        const size_t row = (size_t)(b * SEQ + q0 + r);
        float4 v = make_float4(rna_tf32(o[i][0] * inv), rna_tf32(o[i][1] * inv),
                               rna_tf32(o[i][2] * inv), rna_tf32(o[i][3] * inv));
        *(float4*)&g_C[row * DMODEL + h * HD + 4 * cdx] = v;
    }
}

// ============================================================================
extern "C" void kernel_launch(void* const* d_in, const int* in_sizes, int n_in,
                              void* d_out, int out_size)
{
    const float* X    = (const float*)d_in[0];
    const float* mask = (const float*)d_in[1];
    const float* Wq   = (const float*)d_in[2];
    const float* bq   = (const float*)d_in[3];
    const float* Wk   = (const float*)d_in[4];
    const float* bk   = (const float*)d_in[5];
    const float* Wv   = (const float*)d_in[6];
    const float* bv   = (const float*)d_in[7];
    const float* Wo   = (const float*)d_in[8];
    const float* bo   = (const float*)d_in[9];
    float* out = (float*)d_out;

    cudaFuncSetAttribute(gemm_mma, cudaFuncAttributeMaxDynamicSharedMemorySize, GEMM_SMEM);

    float* dA;     cudaGetSymbolAddress((void**)&dA, g_A);
    float* dQKV;   cudaGetSymbolAddress((void**)&dQKV, g_QKV);
    float* dC;     cudaGetSymbolAddress((void**)&dC, g_C);
    float* dWtQKV; cudaGetSymbolAddress((void**)&dWtQKV, g_WtQKV);
    float* dWtO;   cudaGetSymbolAddress((void**)&dWtO, g_WtO);
    float* dBias;  cudaGetSymbolAddress((void**)&dBias, g_biasQKV);

    // prep: round X, transpose+round weights, concat bias
    prep_round_X<<<(MROWS * DMODEL + 255) / 256, 256>>>(X, dA);
    prep_transpose<<<dim3(32, 32, 4), dim3(32, 8)>>>(Wq, Wk, Wv, Wo);
    prep_bias<<<(NQKV + 255) / 256, 256>>>(bq, bk, bv);

    // QKV projection: [4096,1024] @ [3072,1024]^T -> g_QKV
    gemm_mma<<<dim3(NQKV / 128, MROWS / 128), 256, GEMM_SMEM>>>(dA, dWtQKV, dBias, dQKV, NQKV);
    // flash attention
    attn_kernel<<<dim3(SEQ / BR, BSZ * NH), 256>>>(mask);
    // output projection -> d_out
    gemm_mma<<<dim3(DMODEL / 128, MROWS / 128), 256, GEMM_SMEM>>>(dC, dWtO, bo, out, DMODEL);
}

// round 6
// speedup vs baseline: 3.5654x; 2.4080x over previous
#include <cuda_runtime.h>
#include <math.h>
#include <stdint.h>

#define BSZ 2
#define SEQ 2048
#define DMODEL 1024
#define NH 16
#define HD 64
#define MROWS (BSZ * SEQ)   // 4096
#define NQKV (3 * DMODEL)   // 3072

// -------- scratch (device globals; no allocation allowed) --------
__device__ float g_A[MROWS * DMODEL];        // tf32-rounded X
__device__ float g_QKV[MROWS * NQKV];        // fused Q|K|V, row stride 3072
__device__ float g_C[MROWS * DMODEL];        // attention output (tf32-rounded)
__device__ float g_WtQKV[NQKV * DMODEL];     // transposed+rounded Wq|Wk|Wv  [n][k]
__device__ float g_WtO[DMODEL * DMODEL];     // transposed+rounded Wo        [n][k]
__device__ float g_biasQKV[NQKV];

__device__ __forceinline__ float rna_tf32(float x) {
    uint32_t u;
    asm("cvt.rna.tf32.f32 %0, %1;" : "=r"(u) : "f"(x));
    return __uint_as_float(u);
}
__device__ __forceinline__ float ex2(float x) {
    float r;
    asm("ex2.approx.ftz.f32 %0, %1;" : "=f"(r) : "f"(x));
    return r;
}

__device__ __forceinline__ void mma_tf32(float& c0, float& c1, float& c2, float& c3,
                                         uint32_t a0, uint32_t a1, uint32_t a2, uint32_t a3,
                                         uint32_t b0, uint32_t b1) {
    asm volatile(
        "mma.sync.aligned.m16n8k8.row.col.f32.tf32.tf32.f32 "
        "{%0,%1,%2,%3}, {%4,%5,%6,%7}, {%8,%9}, {%0,%1,%2,%3};"
        : "+f"(c0), "+f"(c1), "+f"(c2), "+f"(c3)
        : "r"(a0), "r"(a1), "r"(a2), "r"(a3), "r"(b0), "r"(b1));
}

// ============================================================================
// tf32 mma.sync GEMM (unchanged from R5): C = A @ Bt^T + bias
// ============================================================================
#define BK 32
#define SM_STRIDE 36
#define SM_ATILE (128 * SM_STRIDE)
#define SM_STAGE (2 * SM_ATILE)
#define GEMM_SMEM (2 * SM_STAGE * 4)

__global__ __launch_bounds__(256) void gemm_mma(
    const float* __restrict__ A, const float* __restrict__ Bt,
    const float* __restrict__ bias, float* __restrict__ C, int Ntot)
{
    extern __shared__ float sm[];
    const int t    = threadIdx.x;
    const int wid  = t >> 5;
    const int lane = t & 31;
    const int wm   = wid >> 2;
    const int wn   = wid & 3;
    const int lrow = lane >> 2;
    const int lcol = lane & 3;
    const int bm = blockIdx.y * 128;
    const int bn = blockIdx.x * 128;

    const float* Ag = A  + (size_t)bm * DMODEL;
    const float* Bg = Bt + (size_t)bn * DMODEL;

    float acc[4][4][4];
#pragma unroll
    for (int mt = 0; mt < 4; mt++)
#pragma unroll
        for (int nt = 0; nt < 4; nt++)
#pragma unroll
            for (int r = 0; r < 4; r++) acc[mt][nt][r] = 0.0f;

    int lrw[4], lk4[4];
#pragma unroll
    for (int j = 0; j < 4; j++) {
        int lin = t + j * 256;
        lrw[j] = lin >> 3;
        lk4[j] = (lin & 7) * 4;
    }

    float4 ra[4], rb[4];
#pragma unroll
    for (int j = 0; j < 4; j++) {
        ra[j] = *(const float4*)&Ag[(size_t)lrw[j] * DMODEL + lk4[j]];
        rb[j] = *(const float4*)&Bg[(size_t)lrw[j] * DMODEL + lk4[j]];
    }
#pragma unroll
    for (int j = 0; j < 4; j++) {
        *(float4*)&sm[lrw[j] * SM_STRIDE + lk4[j]] = ra[j];
        *(float4*)&sm[SM_ATILE + lrw[j] * SM_STRIDE + lk4[j]] = rb[j];
    }
    __syncthreads();

    const int NITER = DMODEL / BK;
    for (int it = 0; it < NITER; it++) {
        const int cur = it & 1;
        if (it + 1 < NITER) {
            const int kb = (it + 1) * BK;
#pragma unroll
            for (int j = 0; j < 4; j++) {
                ra[j] = *(const float4*)&Ag[(size_t)lrw[j] * DMODEL + kb + lk4[j]];
                rb[j] = *(const float4*)&Bg[(size_t)lrw[j] * DMODEL + kb + lk4[j]];
            }
        }

        const float* sa = sm + cur * SM_STAGE;
        const float* sb = sa + SM_ATILE;
#pragma unroll
        for (int ks = 0; ks < 4; ks++) {
            const int k0 = ks * 8 + lcol;
            uint32_t af[4][4];
#pragma unroll
            for (int mt = 0; mt < 4; mt++) {
                const int r0 = (wm * 64 + mt * 16 + lrow) * SM_STRIDE;
                af[mt][0] = __float_as_uint(sa[r0 + k0]);
                af[mt][1] = __float_as_uint(sa[r0 + 8 * SM_STRIDE + k0]);
                af[mt][2] = __float_as_uint(sa[r0 + k0 + 4]);
                af[mt][3] = __float_as_uint(sa[r0 + 8 * SM_STRIDE + k0 + 4]);
            }
#pragma unroll
            for (int nt = 0; nt < 4; nt++) {
                const int n0 = (wn * 32 + nt * 8 + lrow) * SM_STRIDE;
                uint32_t b0 = __float_as_uint(sb[n0 + k0]);
                uint32_t b1 = __float_as_uint(sb[n0 + k0 + 4]);
#pragma unroll
                for (int mt = 0; mt < 4; mt++)
                    mma_tf32(acc[mt][nt][0], acc[mt][nt][1], acc[mt][nt][2], acc[mt][nt][3],
                             af[mt][0], af[mt][1], af[mt][2], af[mt][3], b0, b1);
            }
        }

        if (it + 1 < NITER) {
            float* da = sm + (cur ^ 1) * SM_STAGE;
#pragma unroll
            for (int j = 0; j < 4; j++) {
                *(float4*)&da[lrw[j] * SM_STRIDE + lk4[j]] = ra[j];
                *(float4*)&da[SM_ATILE + lrw[j] * SM_STRIDE + lk4[j]] = rb[j];
            }
        }
        __syncthreads();
    }

#pragma unroll
    for (int mt = 0; mt < 4; mt++) {
#pragma unroll
        for (int nt = 0; nt < 4; nt++) {
            const int row = bm + wm * 64 + mt * 16 + lrow;
            const int col = bn + wn * 32 + nt * 8 + lcol * 2;
            const float bz0 = __ldg(&bias[col]);
            const float bz1 = __ldg(&bias[col + 1]);
            float2 v0 = make_float2(acc[mt][nt][0] + bz0, acc[mt][nt][1] + bz1);
            float2 v1 = make_float2(acc[mt][nt][2] + bz0, acc[mt][nt][3] + bz1);
            *(float2*)&C[(size_t)row * Ntot + col] = v0;
            *(float2*)&C[(size_t)(row + 8) * Ntot + col] = v1;
        }
    }
}

// ============================================================================
// Tensor-core flash attention.
// CTA: 128 q-rows x (b,h); 8 warps; warp w owns rows 16w+g, 16w+g+8.
// Per iter: BC=64 keys. S = QK^T via mma, warp-local online softmax, O += P V.
// Strides: Qs/Ks/Ps 68 (4g+j conflict-free), Vs 72 (8j+g conflict-free).
// ============================================================================
#define ABR 128
#define ABC 64
#define AST 68
#define VST 72
#define OFF_K 8704
#define OFF_V 13056
#define OFF_P 17664
#define OFF_CP 26368
#define ATTN_SMEM ((26368 + 64) * 4)
#define L2E 1.4426950408889634f

__global__ __launch_bounds__(256) void attn_mma(const float* __restrict__ mask)
{
    extern __shared__ float sm[];
    float* Qs  = sm;
    float* Ksm = sm + OFF_K;
    float* Vsm = sm + OFF_V;
    float* Psm = sm + OFF_P;
    float* cpen = sm + OFF_CP;

    const int t = threadIdx.x, w = t >> 5, lane = t & 31;
    const int g = lane >> 2, j = lane & 3;
    const int bh = blockIdx.y, b = bh >> 4, h = bh & 15;
    const int q0 = blockIdx.x * ABR;

    const float* Qg = g_QKV + (size_t)b * SEQ * NQKV + h * HD;
    const float* Kg = Qg + DMODEL;
    const float* Vg = Qg + 2 * DMODEL;

    // load Q tile [128 x 64], tf32-rounded
#pragma unroll
    for (int i = 0; i < 8; i++) {
        int lin = t + i * 256;
        int r = lin >> 4, c4 = (lin & 15) * 4;
        float4 v = *(const float4*)&Qg[(size_t)(q0 + r) * NQKV + c4];
        float4 rv = make_float4(rna_tf32(v.x), rna_tf32(v.y), rna_tf32(v.z), rna_tf32(v.w));
        *(float4*)&Qs[r * AST + c4] = rv;
    }

    const int rbase = w * 16;
    float m0 = -1e30f, m1 = -1e30f, l0 = 0.0f, l1 = 0.0f;
    float o[8][4];
#pragma unroll
    for (int nt = 0; nt < 8; nt++)
#pragma unroll
        for (int r = 0; r < 4; r++) o[nt][r] = 0.0f;

    for (int kb = 0; kb < SEQ / ABC; kb++) {
        const int c0 = kb * ABC;
        // load K [64x64] and V [64x64], tf32-rounded
#pragma unroll
        for (int i = 0; i < 4; i++) {
            int lin = t + i * 256;
            int r = lin >> 4, c4 = (lin & 15) * 4;
            float4 kv = *(const float4*)&Kg[(size_t)(c0 + r) * NQKV + c4];
            float4 vv = *(const float4*)&Vg[(size_t)(c0 + r) * NQKV + c4];
            *(float4*)&Ksm[r * AST + c4] = make_float4(rna_tf32(kv.x), rna_tf32(kv.y),
                                                      rna_tf32(kv.z), rna_tf32(kv.w));
            *(float4*)&Vsm[r * VST + c4] = make_float4(rna_tf32(vv.x), rna_tf32(vv.y),
                                                      rna_tf32(vv.z), rna_tf32(vv.w));
        }
        if (t < ABC) cpen[t] = -1e6f * (1.0f - mask[b * SEQ + c0 + t]);
        __syncthreads();

        // ---- S = Q K^T ----
        float sacc[8][4];
#pragma unroll
        for (int nt = 0; nt < 8; nt++)
#pragma unroll
            for (int r = 0; r < 4; r++) sacc[nt][r] = 0.0f;

#pragma unroll
        for (int ks = 0; ks < 8; ks++) {
            const int k0 = ks * 8;
            const float* ar = &Qs[(rbase + g) * AST + k0 + j];
            uint32_t a0 = __float_as_uint(ar[0]);
            uint32_t a1 = __float_as_uint(ar[8 * AST]);
            uint32_t a2 = __float_as_uint(ar[4]);
            uint32_t a3 = __float_as_uint(ar[8 * AST + 4]);
#pragma unroll
            for (int nt = 0; nt < 8; nt++) {
                const float* br = &Ksm[(nt * 8 + g) * AST + k0 + j];
                uint32_t b0 = __float_as_uint(br[0]);
                uint32_t b1 = __float_as_uint(br[4]);
                mma_tf32(sacc[nt][0], sacc[nt][1], sacc[nt][2], sacc[nt][3],
                         a0, a1, a2, a3, b0, b1);
            }
        }

        // ---- scale + penalty + warp-local online softmax ----
        float mx0 = -1e30f, mx1 = -1e30f;
#pragma unroll
        for (int nt = 0; nt < 8; nt++) {
            const float p0 = cpen[nt * 8 + 2 * j], p1 = cpen[nt * 8 + 2 * j + 1];
            sacc[nt][0] = sacc[nt][0] * 0.125f + p0;
            sacc[nt][1] = sacc[nt][1] * 0.125f + p1;
            sacc[nt][2] = sacc[nt][2] * 0.125f + p0;
            sacc[nt][3] = sacc[nt][3] * 0.125f + p1;
            mx0 = fmaxf(mx0, fmaxf(sacc[nt][0], sacc[nt][1]));
            mx1 = fmaxf(mx1, fmaxf(sacc[nt][2], sacc[nt][3]));
        }
        mx0 = fmaxf(mx0, __shfl_xor_sync(0xffffffffu, mx0, 1));
        mx0 = fmaxf(mx0, __shfl_xor_sync(0xffffffffu, mx0, 2));
        mx1 = fmaxf(mx1, __shfl_xor_sync(0xffffffffu, mx1, 1));
        mx1 = fmaxf(mx1, __shfl_xor_sync(0xffffffffu, mx1, 2));
        const float mn0 = fmaxf(m0, mx0), mn1 = fmaxf(m1, mx1);
        const float al0 = ex2((m0 - mn0) * L2E);
        const float al1 = ex2((m1 - mn1) * L2E);

        float s0 = 0.0f, s1 = 0.0f;
#pragma unroll
        for (int nt = 0; nt < 8; nt++) {
            float p00 = rna_tf32(ex2((sacc[nt][0] - mn0) * L2E));
            float p01 = rna_tf32(ex2((sacc[nt][1] - mn0) * L2E));
            float p10 = rna_tf32(ex2((sacc[nt][2] - mn1) * L2E));
            float p11 = rna_tf32(ex2((sacc[nt][3] - mn1) * L2E));
            sacc[nt][0] = p00; sacc[nt][1] = p01;
            sacc[nt][2] = p10; sacc[nt][3] = p11;
            s0 += p00 + p01;
            s1 += p10 + p11;
        }
        s0 += __shfl_xor_sync(0xffffffffu, s0, 1);
        s0 += __shfl_xor_sync(0xffffffffu, s0, 2);
        s1 += __shfl_xor_sync(0xffffffffu, s1, 1);
        s1 += __shfl_xor_sync(0xffffffffu, s1, 2);
        l0 = l0 * al0 + s0;
        l1 = l1 * al1 + s1;
        m0 = mn0; m1 = mn1;

        // rescale O, store P
#pragma unroll
        for (int nt = 0; nt < 8; nt++) {
            o[nt][0] *= al0; o[nt][1] *= al0;
            o[nt][2] *= al1; o[nt][3] *= al1;
            float* pr = &Psm[(rbase + g) * AST + nt * 8 + 2 * j];
            *(float2*)pr = make_float2(sacc[nt][0], sacc[nt][1]);
            *(float2*)(pr + 8 * AST) = make_float2(sacc[nt][2], sacc[nt][3]);
        }
        __syncthreads();

        // ---- O += P V ----
#pragma unroll
        for (int ks = 0; ks < 8; ks++) {
            const int k0 = ks * 8;
            const float* ar = &Psm[(rbase + g) * AST + k0 + j];
            uint32_t a0 = __float_as_uint(ar[0]);
            uint32_t a1 = __float_as_uint(ar[8 * AST]);
            uint32_t a2 = __float_as_uint(ar[4]);
            uint32_t a3 = __float_as_uint(ar[8 * AST + 4]);
#pragma unroll
            for (int nt = 0; nt < 8; nt++) {
                const float* br = &Vsm[(k0 + j) * VST + nt * 8 + g];
                uint32_t b0 = __float_as_uint(br[0]);
                uint32_t b1 = __float_as_uint(br[4 * VST]);
                mma_tf32(o[nt][0], o[nt][1], o[nt][2], o[nt][3],
                         a0, a1, a2, a3, b0, b1);
            }
        }
        __syncthreads();
    }

    // epilogue: divide by l, tf32-round, write g_C
    const float inv0 = 1.0f / l0, inv1 = 1.0f / l1;
    const size_t row0 = (size_t)(b * SEQ + q0 + rbase + g);
#pragma unroll
    for (int nt = 0; nt < 8; nt++) {
        const int col = h * HD + nt * 8 + 2 * j;
        float2 v0 = make_float2(rna_tf32(o[nt][0] * inv0), rna_tf32(o[nt][1] * inv0));
        float2 v1 = make_float2(rna_tf32(o[nt][2] * inv1), rna_tf32(o[nt][3] * inv1));
        *(float2*)&g_C[row0 * DMODEL + col] = v0;
        *(float2*)&g_C[(row0 + 8) * DMODEL + col] = v1;
    }
}

// ============================================================================
// prep kernels
// ============================================================================
__global__ void prep_round_X(const float* __restrict__ X, float* __restrict__ out) {
    int i = blockIdx.x * blockDim.x + threadIdx.x;
    if (i < MROWS * DMODEL) out[i] = rna_tf32(X[i]);
}

__global__ void prep_transpose(const float* __restrict__ Wq, const float* __restrict__ Wk,
                               const float* __restrict__ Wv, const float* __restrict__ Wo) {
    __shared__ float tile[32][33];
    const int z = blockIdx.z;
    const float* W = (z == 0) ? Wq : (z == 1) ? Wk : (z == 2) ? Wv : Wo;
    float* Dst = (z == 3) ? g_WtO : (g_WtQKV + (size_t)z * DMODEL * DMODEL);
    const int n0 = blockIdx.x * 32, k0 = blockIdx.y * 32;
    const int tx = threadIdx.x, ty0 = threadIdx.y;
#pragma unroll
    for (int ty = ty0; ty < 32; ty += 8)
        tile[ty][tx] = rna_tf32(W[(size_t)(k0 + ty) * DMODEL + n0 + tx]);
    __syncthreads();
#pragma unroll
    for (int ty = ty0; ty < 32; ty += 8)
        Dst[(size_t)(n0 + ty) * DMODEL + k0 + tx] = tile[tx][ty];
}

__global__ void prep_bias(const float* __restrict__ bq, const float* __restrict__ bk,
                          const float* __restrict__ bv) {
    int i = blockIdx.x * blockDim.x + threadIdx.x;
    if (i < NQKV)
        g_biasQKV[i] = (i < 1024) ? bq[i] : (i < 2048) ? bk[i - 1024] : bv[i - 2048];
}

// ============================================================================
extern "C" void kernel_launch(void* const* d_in, const int* in_sizes, int n_in,
                              void* d_out, int out_size)
{
    const float* X    = (const float*)d_in[0];
    const float* mask = (const float*)d_in[1];
    const float* Wq   = (const float*)d_in[2];
    const float* bq   = (const float*)d_in[3];
    const float* Wk   = (const float*)d_in[4];
    const float* bk   = (const float*)d_in[5];
    const float* Wv   = (const float*)d_in[6];
    const float* bv   = (const float*)d_in[7];
    const float* Wo   = (const float*)d_in[8];
    const float* bo   = (const float*)d_in[9];
    float* out = (float*)d_out;

    cudaFuncSetAttribute(gemm_mma, cudaFuncAttributeMaxDynamicSharedMemorySize, GEMM_SMEM);
    cudaFuncSetAttribute(attn_mma, cudaFuncAttributeMaxDynamicSharedMemorySize, ATTN_SMEM);

    float* dA;     cudaGetSymbolAddress((void**)&dA, g_A);
    float* dQKV;   cudaGetSymbolAddress((void**)&dQKV, g_QKV);
    float* dC;     cudaGetSymbolAddress((void**)&dC, g_C);
    float* dWtQKV; cudaGetSymbolAddress((void**)&dWtQKV, g_WtQKV);
    float* dWtO;   cudaGetSymbolAddress((void**)&dWtO, g_WtO);
    float* dBias;  cudaGetSymbolAddress((void**)&dBias, g_biasQKV);

    prep_round_X<<<(MROWS * DMODEL + 255) / 256, 256>>>(X, dA);
    prep_transpose<<<dim3(32, 32, 4), dim3(32, 8)>>>(Wq, Wk, Wv, Wo);
    prep_bias<<<(NQKV + 255) / 256, 256>>>(bq, bk, bv);

    // QKV projection
    gemm_mma<<<dim3(NQKV / 128, MROWS / 128), 256, GEMM_SMEM>>>(dA, dWtQKV, dBias, dQKV, NQKV);
    // tensor-core flash attention
    attn_mma<<<dim3(SEQ / ABR, BSZ * NH), 256, ATTN_SMEM>>>(mask);
    // output projection -> d_out
    gemm_mma<<<dim3(DMODEL / 128, MROWS / 128), 256, GEMM_SMEM>>>(dC, dWtO, bo, out, DMODEL);
}

// round 8
// speedup vs baseline: 3.7074x; 1.0398x over previous
#include <cuda_runtime.h>
#include <math.h>
#include <stdint.h>

#define BSZ 2
#define SEQ 2048
#define DMODEL 1024
#define NH 16
#define HD 64
#define MROWS (BSZ * SEQ)   // 4096
#define NQKV (3 * DMODEL)   // 3072

// -------- scratch (device globals; no allocation allowed) --------
__device__ float g_A[MROWS * DMODEL];        // tf32-rounded X
__device__ float g_QKV[MROWS * NQKV];        // fused Q|K|V, row stride 3072
__device__ float g_C[MROWS * DMODEL];        // attention output (tf32-rounded)
__device__ float g_WtQKV[NQKV * DMODEL];     // transposed+rounded Wq|Wk|Wv  [n][k]
__device__ float g_WtO[DMODEL * DMODEL];     // transposed+rounded Wo        [n][k]
__device__ float g_biasQKV[NQKV];

__device__ __forceinline__ float rna_tf32(float x) {
    uint32_t u;
    asm("cvt.rna.tf32.f32 %0, %1;" : "=r"(u) : "f"(x));
    return __uint_as_float(u);
}
__device__ __forceinline__ float ex2(float x) {
    float r;
    asm("ex2.approx.ftz.f32 %0, %1;" : "=f"(r) : "f"(x));
    return r;
}
__device__ __forceinline__ uint32_t smem_u32(const void* p) {
    uint32_t a;
    asm("{ .reg .u64 t; cvta.to.shared.u64 t, %1; cvt.u32.u64 %0, t; }" : "=r"(a) : "l"(p));
    return a;
}
#define CP_ASYNC16(dst, src) \
    asm volatile("cp.async.ca.shared.global [%0], [%1], 16;" :: "r"(dst), "l"(src))
#define CP_COMMIT() asm volatile("cp.async.commit_group;" ::: "memory")
#define CP_WAIT1()  asm volatile("cp.async.wait_group 1;" ::: "memory")
#define CP_WAIT0()  asm volatile("cp.async.wait_group 0;" ::: "memory")

__device__ __forceinline__ void mma_tf32(float& c0, float& c1, float& c2, float& c3,
                                         uint32_t a0, uint32_t a1, uint32_t a2, uint32_t a3,
                                         uint32_t b0, uint32_t b1) {
    asm volatile(
        "mma.sync.aligned.m16n8k8.row.col.f32.tf32.tf32.f32 "
        "{%0,%1,%2,%3}, {%4,%5,%6,%7}, {%8,%9}, {%0,%1,%2,%3};"
        : "+f"(c0), "+f"(c1), "+f"(c2), "+f"(c3)
        : "r"(a0), "r"(a1), "r"(a2), "r"(a3), "r"(b0), "r"(b1));
}

// ============================================================================
// tf32 mma.sync GEMM, cp.async 2-stage pipeline, 2 CTAs/SM.
// C[M, Ntot] = A[M,1024] @ Bt[Ntot,1024]^T + bias
// ============================================================================
#define BK 32
#define SM_STRIDE 36
#define SM_ATILE (128 * SM_STRIDE)
#define SM_STAGE (2 * SM_ATILE)
#define GEMM_SMEM (2 * SM_STAGE * 4)        // 73728 bytes

__global__ __launch_bounds__(256, 2) void gemm_mma(
    const float* __restrict__ A, const float* __restrict__ Bt,
    const float* __restrict__ bias, float* __restrict__ C, int Ntot)
{
    extern __shared__ float sm[];
    const uint32_t smb = smem_u32(sm);
    const int t    = threadIdx.x;
    const int wid  = t >> 5;
    const int lane = t & 31;
    const int wm   = wid >> 2;
    const int wn   = wid & 3;
    const int lrow = lane >> 2;
    const int lcol = lane & 3;
    const int bm = blockIdx.y * 128;
    const int bn = blockIdx.x * 128;

    const float* Ag = A  + (size_t)bm * DMODEL;
    const float* Bg = Bt + (size_t)bn * DMODEL;

    float acc[4][4][4];
#pragma unroll
    for (int mt = 0; mt < 4; mt++)
#pragma unroll
        for (int nt = 0; nt < 4; nt++)
#pragma unroll
            for (int r = 0; r < 4; r++) acc[mt][nt][r] = 0.0f;

    int lrw[4], lk4[4];
#pragma unroll
    for (int j = 0; j < 4; j++) {
        int lin = t + j * 256;
        lrw[j] = lin >> 3;
        lk4[j] = (lin & 7) * 4;
    }

    const int NITER = DMODEL / BK;    // 32

    // issue cp.async loads of K-slab `it` into stage buffer `stage`
    auto issue = [&](int it, int stage) {
        const int kb = it * BK;
        const uint32_t base = smb + (uint32_t)stage * (SM_STAGE * 4);
#pragma unroll
        for (int j = 0; j < 4; j++) {
            uint32_t d = base + (uint32_t)(lrw[j] * SM_STRIDE + lk4[j]) * 4;
            CP_ASYNC16(d, &Ag[(size_t)lrw[j] * DMODEL + kb + lk4[j]]);
            CP_ASYNC16(d + SM_ATILE * 4, &Bg[(size_t)lrw[j] * DMODEL + kb + lk4[j]]);
        }
        CP_COMMIT();
    };

    issue(0, 0);

    for (int it = 0; it < NITER; it++) {
        if (it + 1 < NITER) {
            issue(it + 1, (it + 1) & 1);
            CP_WAIT1();
        } else {
            CP_WAIT0();
        }
        __syncthreads();

        const float* sa = sm + (it & 1) * SM_STAGE;
        const float* sb = sa + SM_ATILE;
#pragma unroll
        for (int ks = 0; ks < 4; ks++) {
            const int k0 = ks * 8 + lcol;
            uint32_t af[4][4];
#pragma unroll
            for (int mt = 0; mt < 4; mt++) {
                const int r0 = (wm * 64 + mt * 16 + lrow) * SM_STRIDE;
                af[mt][0] = __float_as_uint(sa[r0 + k0]);
                af[mt][1] = __float_as_uint(sa[r0 + 8 * SM_STRIDE + k0]);
                af[mt][2] = __float_as_uint(sa[r0 + k0 + 4]);
                af[mt][3] = __float_as_uint(sa[r0 + 8 * SM_STRIDE + k0 + 4]);
            }
#pragma unroll
            for (int nt = 0; nt < 4; nt++) {
                const int n0 = (wn * 32 + nt * 8 + lrow) * SM_STRIDE;
                uint32_t b0 = __float_as_uint(sb[n0 + k0]);
                uint32_t b1 = __float_as_uint(sb[n0 + k0 + 4]);
#pragma unroll
                for (int mt = 0; mt < 4; mt++)
                    mma_tf32(acc[mt][nt][0], acc[mt][nt][1], acc[mt][nt][2], acc[mt][nt][3],
                             af[mt][0], af[mt][1], af[mt][2], af[mt][3], b0, b1);
            }
        }
        __syncthreads();
    }

#pragma unroll
    for (int mt = 0; mt < 4; mt++) {
#pragma unroll
        for (int nt = 0; nt < 4; nt++) {
            const int row = bm + wm * 64 + mt * 16 + lrow;
            const int col = bn + wn * 32 + nt * 8 + lcol * 2;
            const float bz0 = __ldg(&bias[col]);
            const float bz1 = __ldg(&bias[col + 1]);
            float2 v0 = make_float2(acc[mt][nt][0] + bz0, acc[mt][nt][1] + bz1);
            float2 v1 = make_float2(acc[mt][nt][2] + bz0, acc[mt][nt][3] + bz1);
            *(float2*)&C[(size_t)row * Ntot + col] = v0;
            *(float2*)&C[(size_t)(row + 8) * Ntot + col] = v1;
        }
    }
}

// ============================================================================
// Tensor-core flash attention (R6 layout), now 2 CTAs/SM via launch_bounds.
// ============================================================================
#define ABR 128
#define ABC 64
#define AST 68
#define VST 72
#define OFF_K 8704
#define OFF_V 13056
#define OFF_P 17664
#define OFF_CP 26368
#define ATTN_SMEM ((26368 + 64) * 4)
#define L2E 1.4426950408889634f

__global__ __launch_bounds__(256, 2) void attn_mma(const float* __restrict__ mask)
{
    extern __shared__ float sm[];
    float* Qs  = sm;
    float* Ksm = sm + OFF_K;
    float* Vsm = sm + OFF_V;
    float* Psm = sm + OFF_P;
    float* cpen = sm + OFF_CP;

    const int t = threadIdx.x, w = t >> 5, lane = t & 31;
    const int g = lane >> 2, j = lane & 3;
    const int bh = blockIdx.y, b = bh >> 4, h = bh & 15;
    const int q0 = blockIdx.x * ABR;

    const float* Qg = g_QKV + (size_t)b * SEQ * NQKV + h * HD;
    const float* Kg = Qg + DMODEL;
    const float* Vg = Qg + 2 * DMODEL;

#pragma unroll
    for (int i = 0; i < 8; i++) {
        int lin = t + i * 256;
        int r = lin >> 4, c4 = (lin & 15) * 4;
        float4 v = *(const float4*)&Qg[(size_t)(q0 + r) * NQKV + c4];
        *(float4*)&Qs[r * AST + c4] =
            make_float4(rna_tf32(v.x), rna_tf32(v.y), rna_tf32(v.z), rna_tf32(v.w));
    }

    const int rbase = w * 16;
    float m0 = -1e30f, m1 = -1e30f, l0 = 0.0f, l1 = 0.0f;
    float o[8][4];
#pragma unroll
    for (int nt = 0; nt < 8; nt++)
#pragma unroll
        for (int r = 0; r < 4; r++) o[nt][r] = 0.0f;

    for (int kb = 0; kb < SEQ / ABC; kb++) {
        const int c0 = kb * ABC;
#pragma unroll
        for (int i = 0; i < 4; i++) {
            int lin = t + i * 256;
            int r = lin >> 4, c4 = (lin & 15) * 4;
            float4 kv = *(const float4*)&Kg[(size_t)(c0 + r) * NQKV + c4];
            float4 vv = *(const float4*)&Vg[(size_t)(c0 + r) * NQKV + c4];
            *(float4*)&Ksm[r * AST + c4] = make_float4(rna_tf32(kv.x), rna_tf32(kv.y),
                                                      rna_tf32(kv.z), rna_tf32(kv.w));
            *(float4*)&Vsm[r * VST + c4] = make_float4(rna_tf32(vv.x), rna_tf32(vv.y),
                                                      rna_tf32(vv.z), rna_tf32(vv.w));
        }
        if (t < ABC) cpen[t] = -1e6f * (1.0f - mask[b * SEQ + c0 + t]);
        __syncthreads();

        // ---- S = Q K^T ----
        float sacc[8][4];
#pragma unroll
        for (int nt = 0; nt < 8; nt++)
#pragma unroll
            for (int r = 0; r < 4; r++) sacc[nt][r] = 0.0f;

#pragma unroll
        for (int ks = 0; ks < 8; ks++) {
            const int k0 = ks * 8;
            const float* ar = &Qs[(rbase + g) * AST + k0 + j];
            uint32_t a0 = __float_as_uint(ar[0]);
            uint32_t a1 = __float_as_uint(ar[8 * AST]);
            uint32_t a2 = __float_as_uint(ar[4]);
            uint32_t a3 = __float_as_uint(ar[8 * AST + 4]);
#pragma unroll
            for (int nt = 0; nt < 8; nt++) {
                const float* br = &Ksm[(nt * 8 + g) * AST + k0 + j];
                uint32_t b0 = __float_as_uint(br[0]);
                uint32_t b1 = __float_as_uint(br[4]);
                mma_tf32(sacc[nt][0], sacc[nt][1], sacc[nt][2], sacc[nt][3],
                         a0, a1, a2, a3, b0, b1);
            }
        }

        // ---- scale + penalty + warp-local online softmax ----
        float mx0 = -1e30f, mx1 = -1e30f;
#pragma unroll
        for (int nt = 0; nt < 8; nt++) {
            const float p0 = cpen[nt * 8 + 2 * j], p1 = cpen[nt * 8 + 2 * j + 1];
            sacc[nt][0] = sacc[nt][0] * 0.125f + p0;
            sacc[nt][1] = sacc[nt][1] * 0.125f + p1;
            sacc[nt][2] = sacc[nt][2] * 0.125f + p0;
            sacc[nt][3] = sacc[nt][3] * 0.125f + p1;
            mx0 = fmaxf(mx0, fmaxf(sacc[nt][0], sacc[nt][1]));
            mx1 = fmaxf(mx1, fmaxf(sacc[nt][2], sacc[nt][3]));
        }
        mx0 = fmaxf(mx0, __shfl_xor_sync(0xffffffffu, mx0, 1));
        mx0 = fmaxf(mx0, __shfl_xor_sync(0xffffffffu, mx0, 2));
        mx1 = fmaxf(mx1, __shfl_xor_sync(0xffffffffu, mx1, 1));
        mx1 = fmaxf(mx1, __shfl_xor_sync(0xffffffffu, mx1, 2));
        const float mn0 = fmaxf(m0, mx0), mn1 = fmaxf(m1, mx1);
        const float al0 = ex2((m0 - mn0) * L2E);
        const float al1 = ex2((m1 - mn1) * L2E);

        float s0 = 0.0f, s1 = 0.0f;
#pragma unroll
        for (int nt = 0; nt < 8; nt++) {
            float p00 = rna_tf32(ex2((sacc[nt][0] - mn0) * L2E));
            float p01 = rna_tf32(ex2((sacc[nt][1] - mn0) * L2E));
            float p10 = rna_tf32(ex2((sacc[nt][2] - mn1) * L2E));
            float p11 = rna_tf32(ex2((sacc[nt][3] - mn1) * L2E));
            sacc[nt][0] = p00; sacc[nt][1] = p01;
            sacc[nt][2] = p10; sacc[nt][3] = p11;
            s0 += p00 + p01;
            s1 += p10 + p11;
        }
        s0 += __shfl_xor_sync(0xffffffffu, s0, 1);
        s0 += __shfl_xor_sync(0xffffffffu, s0, 2);
        s1 += __shfl_xor_sync(0xffffffffu, s1, 1);
        s1 += __shfl_xor_sync(0xffffffffu, s1, 2);
        l0 = l0 * al0 + s0;
        l1 = l1 * al1 + s1;
        m0 = mn0; m1 = mn1;

        // rescale O, store P
#pragma unroll
        for (int nt = 0; nt < 8; nt++) {
            o[nt][0] *= al0; o[nt][1] *= al0;
            o[nt][2] *= al1; o[nt][3] *= al1;
            float* pr = &Psm[(rbase + g) * AST + nt * 8 + 2 * j];
            *(float2*)pr = make_float2(sacc[nt][0], sacc[nt][1]);
            *(float2*)(pr + 8 * AST) = make_float2(sacc[nt][2], sacc[nt][3]);
        }
        __syncthreads();

        // ---- O += P V ----
#pragma unroll
        for (int ks = 0; ks < 8; ks++) {
            const int k0 = ks * 8;
            const float* ar = &Psm[(rbase + g) * AST + k0 + j];
            uint32_t a0 = __float_as_uint(ar[0]);
            uint32_t a1 = __float_as_uint(ar[8 * AST]);
            uint32_t a2 = __float_as_uint(ar[4]);
            uint32_t a3 = __float_as_uint(ar[8 * AST + 4]);
#pragma unroll
            for (int nt = 0; nt < 8; nt++) {
                const float* br = &Vsm[(k0 + j) * VST + nt * 8 + g];
                uint32_t b0 = __float_as_uint(br[0]);
                uint32_t b1 = __float_as_uint(br[4 * VST]);
                mma_tf32(o[nt][0], o[nt][1], o[nt][2], o[nt][3],
                         a0, a1, a2, a3, b0, b1);
            }
        }
        __syncthreads();
    }

    const float inv0 = 1.0f / l0, inv1 = 1.0f / l1;
    const size_t row0 = (size_t)(b * SEQ + q0 + rbase + g);
#pragma unroll
    for (int nt = 0; nt < 8; nt++) {
        const int col = h * HD + nt * 8 + 2 * j;
        float2 v0 = make_float2(rna_tf32(o[nt][0] * inv0), rna_tf32(o[nt][1] * inv0));
        float2 v1 = make_float2(rna_tf32(o[nt][2] * inv1), rna_tf32(o[nt][3] * inv1));
        *(float2*)&g_C[row0 * DMODEL + col] = v0;
        *(float2*)&g_C[(row0 + 8) * DMODEL + col] = v1;
    }
}

// ============================================================================
// prep kernels
// ============================================================================
__global__ void prep_round_X(const float* __restrict__ X, float* __restrict__ out) {
    int i = blockIdx.x * blockDim.x + threadIdx.x;
    if (i < MROWS * DMODEL) out[i] = rna_tf32(X[i]);
}

__global__ void prep_transpose(const float* __restrict__ Wq, const float* __restrict__ Wk,
                               const float* __restrict__ Wv, const float* __restrict__ Wo) {
    __shared__ float tile[32][33];
    const int z = blockIdx.z;
    const float* W = (z == 0) ? Wq : (z == 1) ? Wk : (z == 2) ? Wv : Wo;
    float* Dst = (z == 3) ? g_WtO : (g_WtQKV + (size_t)z * DMODEL * DMODEL);
    const int n0 = blockIdx.x * 32, k0 = blockIdx.y * 32;
    const int tx = threadIdx.x, ty0 = threadIdx.y;
#pragma unroll
    for (int ty = ty0; ty < 32; ty += 8)
        tile[ty][tx] = rna_tf32(W[(size_t)(k0 + ty) * DMODEL + n0 + tx]);
    __syncthreads();
#pragma unroll
    for (int ty = ty0; ty < 32; ty += 8)
        Dst[(size_t)(n0 + ty) * DMODEL + k0 + tx] = tile[tx][ty];
}

__global__ void prep_bias(const float* __restrict__ bq, const float* __restrict__ bk,
                          const float* __restrict__ bv) {
    int i = blockIdx.x * blockDim.x + threadIdx.x;
    if (i < NQKV)
        g_biasQKV[i] = (i < 1024) ? bq[i] : (i < 2048) ? bk[i - 1024] : bv[i - 2048];
}

// ============================================================================
extern "C" void kernel_launch(void* const* d_in, const int* in_sizes, int n_in,
                              void* d_out, int out_size)
{
    const float* X    = (const float*)d_in[0];
    const float* mask = (const float*)d_in[1];
    const float* Wq   = (const float*)d_in[2];
    const float* bq   = (const float*)d_in[3];
    const float* Wk   = (const float*)d_in[4];
    const float* bk   = (const float*)d_in[5];
    const float* Wv   = (const float*)d_in[6];
    const float* bv   = (const float*)d_in[7];
    const float* Wo   = (const float*)d_in[8];
    const float* bo   = (const float*)d_in[9];
    float* out = (float*)d_out;

    cudaFuncSetAttribute(gemm_mma, cudaFuncAttributeMaxDynamicSharedMemorySize, GEMM_SMEM);
    cudaFuncSetAttribute(attn_mma, cudaFuncAttributeMaxDynamicSharedMemorySize, ATTN_SMEM);

    float* dA;     cudaGetSymbolAddress((void**)&dA, g_A);
    float* dQKV;   cudaGetSymbolAddress((void**)&dQKV, g_QKV);
    float* dC;     cudaGetSymbolAddress((void**)&dC, g_C);
    float* dWtQKV; cudaGetSymbolAddress((void**)&dWtQKV, g_WtQKV);
    float* dWtO;   cudaGetSymbolAddress((void**)&dWtO, g_WtO);
    float* dBias;  cudaGetSymbolAddress((void**)&dBias, g_biasQKV);

    prep_round_X<<<(MROWS * DMODEL + 255) / 256, 256>>>(X, dA);
    prep_transpose<<<dim3(32, 32, 4), dim3(32, 8)>>>(Wq, Wk, Wv, Wo);
    prep_bias<<<(NQKV + 255) / 256, 256>>>(bq, bk, bv);

    // QKV projection
    gemm_mma<<<dim3(NQKV / 128, MROWS / 128), 256, GEMM_SMEM>>>(dA, dWtQKV, dBias, dQKV, NQKV);
    // tensor-core flash attention
    attn_mma<<<dim3(SEQ / ABR, BSZ * NH), 256, ATTN_SMEM>>>(mask);
    // output projection -> d_out
    gemm_mma<<<dim3(DMODEL / 128, MROWS / 128), 256, GEMM_SMEM>>>(dC, dWtO, bo, out, DMODEL);
}

// round 10
// speedup vs baseline: 4.2906x; 1.1573x over previous
#include <cuda_runtime.h>
#include <math.h>
#include <stdint.h>

#define BSZ 2
#define SEQ 2048
#define DMODEL 1024
#define NH 16
#define HD 64
#define MROWS (BSZ * SEQ)   // 4096
#define NQKV (3 * DMODEL)   // 3072

// -------- scratch (device globals; no allocation allowed) --------
__device__ float g_A[MROWS * DMODEL];        // tf32-rounded X
__device__ float g_QKV[MROWS * NQKV];        // fused Q|K|V (tf32-rounded), stride 3072
__device__ float g_C[MROWS * DMODEL];        // attention output (tf32-rounded)
__device__ float g_WtQKV[NQKV * DMODEL];     // transposed+rounded Wq|Wk|Wv [n][k]
__device__ float g_WtO[DMODEL * DMODEL];     // transposed+rounded Wo       [n][k]
__device__ float g_biasQKV[NQKV];

__device__ __forceinline__ float rna_tf32(float x) {
    uint32_t u;
    asm("cvt.rna.tf32.f32 %0, %1;" : "=r"(u) : "f"(x));
    return __uint_as_float(u);
}
__device__ __forceinline__ float ex2(float x) {
    float r;
    asm("ex2.approx.ftz.f32 %0, %1;" : "=f"(r) : "f"(x));
    return r;
}
__device__ __forceinline__ uint32_t smem_u32(const void* p) {
    uint32_t a;
    asm("{ .reg .u64 t; cvta.to.shared.u64 t, %1; cvt.u32.u64 %0, t; }" : "=r"(a) : "l"(p));
    return a;
}
#define CP_ASYNC16(dst, src) \
    asm volatile("cp.async.ca.shared.global [%0], [%1], 16;" :: "r"(dst), "l"(src))
#define CP_COMMIT() asm volatile("cp.async.commit_group;" ::: "memory")
#define CP_WAIT1()  asm volatile("cp.async.wait_group 1;" ::: "memory")
#define CP_WAIT0()  asm volatile("cp.async.wait_group 0;" ::: "memory")

__device__ __forceinline__ void mma_tf32(float& c0, float& c1, float& c2, float& c3,
                                         uint32_t a0, uint32_t a1, uint32_t a2, uint32_t a3,
                                         uint32_t b0, uint32_t b1) {
    asm volatile(
        "mma.sync.aligned.m16n8k8.row.col.f32.tf32.tf32.f32 "
        "{%0,%1,%2,%3}, {%4,%5,%6,%7}, {%8,%9}, {%0,%1,%2,%3};"
        : "+f"(c0), "+f"(c1), "+f"(c2), "+f"(c3)
        : "r"(a0), "r"(a1), "r"(a2), "r"(a3), "r"(b0), "r"(b1));
}

// ============================================================================
// tf32 mma.sync GEMM: C[M, Ntot] = A[M,1024] @ Bt[Ntot,1024]^T + bias
// CTA tile 128(M) x 256(N), BK=32; 8 warps = 2(m) x 4(n); warp tile 64x64
// (mt=4, nt=8). Per k-step: 32 LDS.32 vs 32 HMMA -> crossbar/tensor balanced.
// ============================================================================
#define BK 32
#define SM_STRIDE 36
#define SMG_A (128 * SM_STRIDE)             // 4608 floats
#define SMG_B (256 * SM_STRIDE)             // 9216 floats
#define SMG_STAGE (SMG_A + SMG_B)           // 13824 floats
#define GEMM_SMEM (2 * SMG_STAGE * 4)       // 110592 bytes

__global__ __launch_bounds__(256, 1) void gemm_mma(
    const float* __restrict__ A, const float* __restrict__ Bt,
    const float* __restrict__ bias, float* __restrict__ C, int Ntot, int roundC)
{
    extern __shared__ float sm[];
    const uint32_t smb = smem_u32(sm);
    const int t    = threadIdx.x;
    const int wid  = t >> 5;
    const int lane = t & 31;
    const int wm   = wid >> 2;     // 0..1   -> rows wm*64
    const int wn   = wid & 3;      // 0..3   -> cols wn*64
    const int g    = lane >> 2;    // 0..7
    const int j    = lane & 3;     // 0..3
    const int bm = blockIdx.y * 128;
    const int bn = blockIdx.x * 256;

    const float* Ag = A  + (size_t)bm * DMODEL;
    const float* Bg = Bt + (size_t)bn * DMODEL;

    float acc[4][8][4];
#pragma unroll
    for (int mt = 0; mt < 4; mt++)
#pragma unroll
        for (int nt = 0; nt < 8; nt++)
#pragma unroll
            for (int r = 0; r < 4; r++) acc[mt][nt][r] = 0.0f;

    // loader mapping: A 1024 float4 (4/thread), B 2048 float4 (8/thread)
    const int arw = (t + 0 * 256) >> 3;        // pattern reused with offsets
    const int ak4 = (t & 7) * 4;
    (void)arw; (void)ak4;

    auto issue = [&](int it, int stage) {
        const int kb = it * BK;
        const uint32_t base = smb + (uint32_t)stage * (SMG_STAGE * 4);
#pragma unroll
        for (int jj = 0; jj < 4; jj++) {
            int lin = t + jj * 256;
            int row = lin >> 3, k4 = (lin & 7) * 4;
            CP_ASYNC16(base + (uint32_t)(row * SM_STRIDE + k4) * 4,
                       &Ag[(size_t)row * DMODEL + kb + k4]);
        }
#pragma unroll
        for (int jj = 0; jj < 8; jj++) {
            int lin = t + jj * 256;
            int row = lin >> 3, k4 = (lin & 7) * 4;
            CP_ASYNC16(base + (uint32_t)(SMG_A + row * SM_STRIDE + k4) * 4,
                       &Bg[(size_t)row * DMODEL + kb + k4]);
        }
        CP_COMMIT();
    };

    const int NITER = DMODEL / BK;    // 32
    issue(0, 0);

    for (int it = 0; it < NITER; it++) {
        if (it + 1 < NITER) { issue(it + 1, (it + 1) & 1); CP_WAIT1(); }
        else                { CP_WAIT0(); }
        __syncthreads();

        const float* sa = sm + (it & 1) * SMG_STAGE;
        const float* sb = sa + SMG_A;
#pragma unroll
        for (int ks = 0; ks < 4; ks++) {
            const int k0 = ks * 8 + j;
            uint32_t af[4][4];
#pragma unroll
            for (int mt = 0; mt < 4; mt++) {
                const int r0 = (wm * 64 + mt * 16 + g) * SM_STRIDE;
                af[mt][0] = __float_as_uint(sa[r0 + k0]);
                af[mt][1] = __float_as_uint(sa[r0 + 8 * SM_STRIDE + k0]);
                af[mt][2] = __float_as_uint(sa[r0 + k0 + 4]);
                af[mt][3] = __float_as_uint(sa[r0 + 8 * SM_STRIDE + k0 + 4]);
            }
#pragma unroll
            for (int nt = 0; nt < 8; nt++) {
                const int n0 = (wn * 64 + nt * 8 + g) * SM_STRIDE;
                uint32_t b0 = __float_as_uint(sb[n0 + k0]);
                uint32_t b1 = __float_as_uint(sb[n0 + k0 + 4]);
#pragma unroll
                for (int mt = 0; mt < 4; mt++)
                    mma_tf32(acc[mt][nt][0], acc[mt][nt][1], acc[mt][nt][2], acc[mt][nt][3],
                             af[mt][0], af[mt][1], af[mt][2], af[mt][3], b0, b1);
            }
        }
        __syncthreads();
    }

    // epilogue
#pragma unroll
    for (int mt = 0; mt < 4; mt++) {
#pragma unroll
        for (int nt = 0; nt < 8; nt++) {
            const int row = bm + wm * 64 + mt * 16 + g;
            const int col = bn + wn * 64 + nt * 8 + j * 2;
            const float bz0 = __ldg(&bias[col]);
            const float bz1 = __ldg(&bias[col + 1]);
            float r00 = acc[mt][nt][0] + bz0, r01 = acc[mt][nt][1] + bz1;
            float r10 = acc[mt][nt][2] + bz0, r11 = acc[mt][nt][3] + bz1;
            if (roundC) {
                r00 = rna_tf32(r00); r01 = rna_tf32(r01);
                r10 = rna_tf32(r10); r11 = rna_tf32(r11);
            }
            *(float2*)&C[(size_t)row * Ntot + col] = make_float2(r00, r01);
            *(float2*)&C[(size_t)(row + 8) * Ntot + col] = make_float2(r10, r11);
        }
    }
}

// ============================================================================
// Tensor-core flash attention. CTA = 256 q-rows, 8 warps x 32 rows (mt=2).
// K/V pre-rounded upstream -> cp.async double-buffered loads. Q loaded once.
// ============================================================================
#define ABR 256
#define ABC 64
#define AST 68
#define VST 72
#define OFF_Q  0
#define OFF_K0 17408
#define OFF_V0 21760
#define OFF_K1 26368
#define OFF_V1 30720
#define OFF_P  35328
#define OFF_CP 52736            // cpen[2][64]
#define ATTN_SMEM ((52736 + 128) * 4)   // 211456 bytes
#define L2E 1.4426950408889634f

__global__ __launch_bounds__(256, 1) void attn_mma(const float* __restrict__ mask)
{
    extern __shared__ float sm[];
    const uint32_t smb = smem_u32(sm);
    float* Qs  = sm + OFF_Q;
    float* Psm = sm + OFF_P;

    const int t = threadIdx.x, w = t >> 5, lane = t & 31;
    const int g = lane >> 2, j = lane & 3;
    const int bh = blockIdx.y, b = bh >> 4, h = bh & 15;
    const int q0 = blockIdx.x * ABR;

    const float* Qg = g_QKV + (size_t)b * SEQ * NQKV + h * HD;
    const float* Kg = Qg + DMODEL;
    const float* Vg = Qg + 2 * DMODEL;

    // Q tile [256 x 64] via cp.async (already tf32-rounded)
#pragma unroll
    for (int i = 0; i < 16; i++) {
        int lin = t + i * 256;
        int r = lin >> 4, c4 = (lin & 15) * 4;
        CP_ASYNC16(smb + (uint32_t)(OFF_Q + r * AST + c4) * 4,
                   &Qg[(size_t)(q0 + r) * NQKV + c4]);
    }
    CP_COMMIT();

    // K/V issue for tile `kb` into stage s
    auto issue_kv = [&](int kb, int s) {
        const int c0 = kb * ABC;
        const uint32_t kbase = smb + (uint32_t)(s ? OFF_K1 : OFF_K0) * 4;
        const uint32_t vbase = smb + (uint32_t)(s ? OFF_V1 : OFF_V0) * 4;
#pragma unroll
        for (int i = 0; i < 4; i++) {
            int lin = t + i * 256;
            int r = lin >> 4, c4 = (lin & 15) * 4;
            CP_ASYNC16(kbase + (uint32_t)(r * AST + c4) * 4,
                       &Kg[(size_t)(c0 + r) * NQKV + c4]);
            CP_ASYNC16(vbase + (uint32_t)(r * VST + c4) * 4,
                       &Vg[(size_t)(c0 + r) * NQKV + c4]);
        }
        if (t < ABC)
            sm[OFF_CP + s * 64 + t] = -1e6f * (1.0f - mask[b * SEQ + c0 + t]);
        CP_COMMIT();
    };

    issue_kv(0, 0);

    const int rb = w * 32;           // warp's 32 rows
    float mst[2] = {-1e30f, -1e30f}, mst1[2] = {-1e30f, -1e30f};
    float lst[2] = {0.0f, 0.0f},     lst1[2] = {0.0f, 0.0f};
    float o[2][8][4];
#pragma unroll
    for (int mt = 0; mt < 2; mt++)
#pragma unroll
        for (int nt = 0; nt < 8; nt++)
#pragma unroll
            for (int r = 0; r < 4; r++) o[mt][nt][r] = 0.0f;

    const int NB = SEQ / ABC;        // 32
    for (int kb = 0; kb < NB; kb++) {
        const int cur = kb & 1;
        if (kb + 1 < NB) { issue_kv(kb + 1, cur ^ 1); CP_WAIT1(); }
        else             { CP_WAIT0(); }
        __syncthreads();

        const float* Ksm = sm + (cur ? OFF_K1 : OFF_K0);
        const float* Vsm = sm + (cur ? OFF_V1 : OFF_V0);
        const float* cp  = sm + OFF_CP + cur * 64;

        // ---- S = Q K^T ----
        float sacc[2][8][4];
#pragma unroll
        for (int mt = 0; mt < 2; mt++)
#pragma unroll
            for (int nt = 0; nt < 8; nt++)
#pragma unroll
                for (int r = 0; r < 4; r++) sacc[mt][nt][r] = 0.0f;

#pragma unroll
        for (int ks = 0; ks < 8; ks++) {
            const int k0 = ks * 8;
            uint32_t af[2][4];
#pragma unroll
            for (int mt = 0; mt < 2; mt++) {
                const float* ar = &Qs[(rb + mt * 16 + g) * AST + k0 + j];
                af[mt][0] = __float_as_uint(ar[0]);
                af[mt][1] = __float_as_uint(ar[8 * AST]);
                af[mt][2] = __float_as_uint(ar[4]);
                af[mt][3] = __float_as_uint(ar[8 * AST + 4]);
            }
#pragma unroll
            for (int nt = 0; nt < 8; nt++) {
                const float* br = &Ksm[(nt * 8 + g) * AST + k0 + j];
                uint32_t b0 = __float_as_uint(br[0]);
                uint32_t b1 = __float_as_uint(br[4]);
#pragma unroll
                for (int mt = 0; mt < 2; mt++)
                    mma_tf32(sacc[mt][nt][0], sacc[mt][nt][1], sacc[mt][nt][2], sacc[mt][nt][3],
                             af[mt][0], af[mt][1], af[mt][2], af[mt][3], b0, b1);
            }
        }

        // ---- softmax per mt-frag (rows g / g+8) ----
#pragma unroll
        for (int mt = 0; mt < 2; mt++) {
            float mx0 = -1e30f, mx1 = -1e30f;
#pragma unroll
            for (int nt = 0; nt < 8; nt++) {
                const float p0 = cp[nt * 8 + 2 * j], p1 = cp[nt * 8 + 2 * j + 1];
                sacc[mt][nt][0] = sacc[mt][nt][0] * 0.125f + p0;
                sacc[mt][nt][1] = sacc[mt][nt][1] * 0.125f + p1;
                sacc[mt][nt][2] = sacc[mt][nt][2] * 0.125f + p0;
                sacc[mt][nt][3] = sacc[mt][nt][3] * 0.125f + p1;
                mx0 = fmaxf(mx0, fmaxf(sacc[mt][nt][0], sacc[mt][nt][1]));
                mx1 = fmaxf(mx1, fmaxf(sacc[mt][nt][2], sacc[mt][nt][3]));
            }
            mx0 = fmaxf(mx0, __shfl_xor_sync(0xffffffffu, mx0, 1));
            mx0 = fmaxf(mx0, __shfl_xor_sync(0xffffffffu, mx0, 2));
            mx1 = fmaxf(mx1, __shfl_xor_sync(0xffffffffu, mx1, 1));
            mx1 = fmaxf(mx1, __shfl_xor_sync(0xffffffffu, mx1, 2));
            const float m0old = mt ? mst1[0] : mst[0];   // row g state
            const float m1old = mt ? mst1[1] : mst[1];   // row g+8 state
            const float mn0 = fmaxf(m0old, mx0), mn1 = fmaxf(m1old, mx1);
            const float al0 = ex2((m0old - mn0) * L2E);
            const float al1 = ex2((m1old - mn1) * L2E);

            float s0 = 0.0f, s1 = 0.0f;
#pragma unroll
            for (int nt = 0; nt < 8; nt++) {
                float p00 = rna_tf32(ex2((sacc[mt][nt][0] - mn0) * L2E));
                float p01 = rna_tf32(ex2((sacc[mt][nt][1] - mn0) * L2E));
                float p10 = rna_tf32(ex2((sacc[mt][nt][2] - mn1) * L2E));
                float p11 = rna_tf32(ex2((sacc[mt][nt][3] - mn1) * L2E));
                s0 += p00 + p01;
                s1 += p10 + p11;
                o[mt][nt][0] *= al0; o[mt][nt][1] *= al0;
                o[mt][nt][2] *= al1; o[mt][nt][3] *= al1;
                float* pr = &Psm[(rb + mt * 16 + g) * AST + nt * 8 + 2 * j];
                *(float2*)pr = make_float2(p00, p01);
                *(float2*)(pr + 8 * AST) = make_float2(p10, p11);
            }
            s0 += __shfl_xor_sync(0xffffffffu, s0, 1);
            s0 += __shfl_xor_sync(0xffffffffu, s0, 2);
            s1 += __shfl_xor_sync(0xffffffffu, s1, 1);
            s1 += __shfl_xor_sync(0xffffffffu, s1, 2);
            if (mt == 0) {
                lst[0] = lst[0] * al0 + s0; lst[1] = lst[1] * al1 + s1;
                mst[0] = mn0; mst[1] = mn1;
            } else {
                lst1[0] = lst1[0] * al0 + s0; lst1[1] = lst1[1] * al1 + s1;
                mst1[0] = mn0; mst1[1] = mn1;
            }
        }
        __syncthreads();

        // ---- O += P V ----
#pragma unroll
        for (int ks = 0; ks < 8; ks++) {
            const int k0 = ks * 8;
            uint32_t af[2][4];
#pragma unroll
            for (int mt = 0; mt < 2; mt++) {
                const float* ar = &Psm[(rb + mt * 16 + g) * AST + k0 + j];
                af[mt][0] = __float_as_uint(ar[0]);
                af[mt][1] = __float_as_uint(ar[8 * AST]);
                af[mt][2] = __float_as_uint(ar[4]);
                af[mt][3] = __float_as_uint(ar[8 * AST + 4]);
            }
#pragma unroll
            for (int nt = 0; nt < 8; nt++) {
                const float* br = &Vsm[(k0 + j) * VST + nt * 8 + g];
                uint32_t b0 = __float_as_uint(br[0]);
                uint32_t b1 = __float_as_uint(br[4 * VST]);
#pragma unroll
                for (int mt = 0; mt < 2; mt++)
                    mma_tf32(o[mt][nt][0], o[mt][nt][1], o[mt][nt][2], o[mt][nt][3],
                             af[mt][0], af[mt][1], af[mt][2], af[mt][3], b0, b1);
            }
        }
        __syncthreads();
    }

    // epilogue
#pragma unroll
    for (int mt = 0; mt < 2; mt++) {
        const float inv0 = 1.0f / (mt ? lst1[0] : lst[0]);
        const float inv1 = 1.0f / (mt ? lst1[1] : lst[1]);
        const size_t row0 = (size_t)(b * SEQ + q0 + rb + mt * 16 + g);
#pragma unroll
        for (int nt = 0; nt < 8; nt++) {
            const int col = h * HD + nt * 8 + 2 * j;
            float2 v0 = make_float2(rna_tf32(o[mt][nt][0] * inv0), rna_tf32(o[mt][nt][1] * inv0));
            float2 v1 = make_float2(rna_tf32(o[mt][nt][2] * inv1), rna_tf32(o[mt][nt][3] * inv1));
            *(float2*)&g_C[row0 * DMODEL + col] = v0;
            *(float2*)&g_C[(row0 + 8) * DMODEL + col] = v1;
        }
    }
}

// ============================================================================
// prep kernels
// ============================================================================
__global__ void prep_round_X(const float* __restrict__ X, float* __restrict__ out) {
    int i = blockIdx.x * blockDim.x + threadIdx.x;
    if (i < MROWS * DMODEL) out[i] = rna_tf32(X[i]);
}

__global__ void prep_transpose(const float* __restrict__ Wq, const float* __restrict__ Wk,
                               const float* __restrict__ Wv, const float* __restrict__ Wo) {
    __shared__ float tile[32][33];
    const int z = blockIdx.z;
    const float* W = (z == 0) ? Wq : (z == 1) ? Wk : (z == 2) ? Wv : Wo;
    float* Dst = (z == 3) ? g_WtO : (g_WtQKV + (size_t)z * DMODEL * DMODEL);
    const int n0 = blockIdx.x * 32, k0 = blockIdx.y * 32;
    const int tx = threadIdx.x, ty0 = threadIdx.y;
#pragma unroll
    for (int ty = ty0; ty < 32; ty += 8)
        tile[ty][tx] = rna_tf32(W[(size_t)(k0 + ty) * DMODEL + n0 + tx]);
    __syncthreads();
#pragma unroll
    for (int ty = ty0; ty < 32; ty += 8)
        Dst[(size_t)(n0 + ty) * DMODEL + k0 + tx] = tile[tx][ty];
}

__global__ void prep_bias(const float* __restrict__ bq, const float* __restrict__ bk,
                          const float* __restrict__ bv) {
    int i = blockIdx.x * blockDim.x + threadIdx.x;
    if (i < NQKV)
        g_biasQKV[i] = (i < 1024) ? bq[i] : (i < 2048) ? bk[i - 1024] : bv[i - 2048];
}

// ============================================================================
extern "C" void kernel_launch(void* const* d_in, const int* in_sizes, int n_in,
                              void* d_out, int out_size)
{
    const float* X    = (const float*)d_in[0];
    const float* mask = (const float*)d_in[1];
    const float* Wq   = (const float*)d_in[2];
    const float* bq   = (const float*)d_in[3];
    const float* Wk   = (const float*)d_in[4];
    const float* bk   = (const float*)d_in[5];
    const float* Wv   = (const float*)d_in[6];
    const float* bv   = (const float*)d_in[7];
    const float* Wo   = (const float*)d_in[8];
    const float* bo   = (const float*)d_in[9];
    float* out = (float*)d_out;

    cudaFuncSetAttribute(gemm_mma, cudaFuncAttributeMaxDynamicSharedMemorySize, GEMM_SMEM);
    cudaFuncSetAttribute(attn_mma, cudaFuncAttributeMaxDynamicSharedMemorySize, ATTN_SMEM);

    float* dA;     cudaGetSymbolAddress((void**)&dA, g_A);
    float* dQKV;   cudaGetSymbolAddress((void**)&dQKV, g_QKV);
    float* dC;     cudaGetSymbolAddress((void**)&dC, g_C);
    float* dWtQKV; cudaGetSymbolAddress((void**)&dWtQKV, g_WtQKV);
    float* dWtO;   cudaGetSymbolAddress((void**)&dWtO, g_WtO);
    float* dBias;  cudaGetSymbolAddress((void**)&dBias, g_biasQKV);

    prep_round_X<<<(MROWS * DMODEL + 255) / 256, 256>>>(X, dA);
    prep_transpose<<<dim3(32, 32, 4), dim3(32, 8)>>>(Wq, Wk, Wv, Wo);
    prep_bias<<<(NQKV + 255) / 256, 256>>>(bq, bk, bv);

    // QKV projection (output tf32-rounded for attention)
    gemm_mma<<<dim3(NQKV / 256, MROWS / 128), 256, GEMM_SMEM>>>(dA, dWtQKV, dBias, dQKV, NQKV, 1);
    // tensor-core flash attention
    attn_mma<<<dim3(SEQ / ABR, BSZ * NH), 256, ATTN_SMEM>>>(mask);
    // output projection -> d_out
    gemm_mma<<<dim3(DMODEL / 256, MROWS / 128), 256, GEMM_SMEM>>>(dC, dWtO, bo, out, DMODEL, 0);
}

// round 11
// speedup vs baseline: 4.3673x; 1.0179x over previous
#include <cuda_runtime.h>
#include <math.h>
#include <stdint.h>

#define BSZ 2
#define SEQ 2048
#define DMODEL 1024
#define NH 16
#define HD 64
#define MROWS (BSZ * SEQ)   // 4096
#define NQKV (3 * DMODEL)   // 3072
#define L2E 1.4426950408889634f
#define QSCALE (0.125f * L2E)

// -------- scratch (device globals; no allocation allowed) --------
__device__ float g_A[MROWS * DMODEL];        // tf32-rounded X
__device__ float g_QKV[MROWS * NQKV];        // Q(pre-scaled)|K|V tf32-rounded
__device__ float g_C[MROWS * DMODEL];        // attention output (tf32-rounded)
__device__ float g_WtQKV[NQKV * DMODEL];     // transposed+rounded Wq|Wk|Wv [n][k]
__device__ float g_WtO[DMODEL * DMODEL];     // transposed+rounded Wo       [n][k]
__device__ float g_biasQKV[NQKV];

__device__ __forceinline__ float rna_tf32(float x) {
    uint32_t u;
    asm("cvt.rna.tf32.f32 %0, %1;" : "=r"(u) : "f"(x));
    return __uint_as_float(u);
}
__device__ __forceinline__ float ex2(float x) {
    float r;
    asm("ex2.approx.ftz.f32 %0, %1;" : "=f"(r) : "f"(x));
    return r;
}
__device__ __forceinline__ uint32_t smem_u32(const void* p) {
    uint32_t a;
    asm("{ .reg .u64 t; cvta.to.shared.u64 t, %1; cvt.u32.u64 %0, t; }" : "=r"(a) : "l"(p));
    return a;
}
#define CP_ASYNC16(dst, src) \
    asm volatile("cp.async.ca.shared.global [%0], [%1], 16;" :: "r"(dst), "l"(src))
#define CP_COMMIT() asm volatile("cp.async.commit_group;" ::: "memory")
#define CP_WAIT1()  asm volatile("cp.async.wait_group 1;" ::: "memory")
#define CP_WAIT0()  asm volatile("cp.async.wait_group 0;" ::: "memory")

__device__ __forceinline__ void mma_tf32(float& c0, float& c1, float& c2, float& c3,
                                         uint32_t a0, uint32_t a1, uint32_t a2, uint32_t a3,
                                         uint32_t b0, uint32_t b1) {
    asm volatile(
        "mma.sync.aligned.m16n8k8.row.col.f32.tf32.tf32.f32 "
        "{%0,%1,%2,%3}, {%4,%5,%6,%7}, {%8,%9}, {%0,%1,%2,%3};"
        : "+f"(c0), "+f"(c1), "+f"(c2), "+f"(c3)
        : "r"(a0), "r"(a1), "r"(a2), "r"(a3), "r"(b0), "r"(b1));
}
// type-agnostic 16B-row matrix load: 4 m8n8 tiles of 32-bit data
__device__ __forceinline__ void ldsm_x4(uint32_t& r0, uint32_t& r1, uint32_t& r2, uint32_t& r3,
                                        uint32_t addr) {
    asm volatile("ldmatrix.sync.aligned.m8n8.x4.shared.b16 {%0,%1,%2,%3}, [%4];"
                 : "=r"(r0), "=r"(r1), "=r"(r2), "=r"(r3) : "r"(addr));
}

// ============================================================================
// tf32 mma.sync GEMM: C[M, Ntot] = A[M,1024] @ Bt[Ntot,1024]^T + bias
// CTA 128x256, BK=32, 8 warps (2m x 4n), warp tile 64x64.
// Fragments via ldmatrix.x4 (stride 36 => conflict-free).
// roundC: 1 => tf32-round output; Q columns (col<1024) also scaled by QSCALE.
// ============================================================================
#define BK 32
#define SM_STRIDE 36
#define SMG_A (128 * SM_STRIDE)             // 4608 floats
#define SMG_B (256 * SM_STRIDE)             // 9216 floats
#define SMG_STAGE (SMG_A + SMG_B)           // 13824 floats
#define GEMM_SMEM (2 * SMG_STAGE * 4)       // 110592 bytes

__global__ __launch_bounds__(256, 1) void gemm_mma(
    const float* __restrict__ A, const float* __restrict__ Bt,
    const float* __restrict__ bias, float* __restrict__ C, int Ntot, int roundC)
{
    extern __shared__ float sm[];
    const uint32_t smb = smem_u32(sm);
    const int t    = threadIdx.x;
    const int wid  = t >> 5;
    const int lane = t & 31;
    const int wm   = wid >> 2;     // 0..1
    const int wn   = wid & 3;      // 0..3
    const int g    = lane >> 2;
    const int j    = lane & 3;
    const int bm = blockIdx.y * 128;
    const int bn = blockIdx.x * 256;

    const float* Ag = A  + (size_t)bm * DMODEL;
    const float* Bg = Bt + (size_t)bn * DMODEL;

    float acc[4][8][4];
#pragma unroll
    for (int mt = 0; mt < 4; mt++)
#pragma unroll
        for (int nt = 0; nt < 8; nt++)
#pragma unroll
            for (int r = 0; r < 4; r++) acc[mt][nt][r] = 0.0f;

    // ldmatrix lane-address offsets (bytes, within a stage)
    uint32_t aoff[4], boff[4];
    {
        const int arow = lane & 15;            // tile row
        const int acol = (lane >> 4) * 4;      // 0 or 4 floats
#pragma unroll
        for (int mt = 0; mt < 4; mt++)
            aoff[mt] = (uint32_t)(((wm * 64 + mt * 16 + arow) * SM_STRIDE + acol) * 4);
        const int brow = ((lane >> 4) & 1) * 8 + (lane & 7);
        const int bcol = ((lane >> 3) & 1) * 4;
#pragma unroll
        for (int p = 0; p < 4; p++)
            boff[p] = (uint32_t)((SMG_A + (wn * 64 + p * 16 + brow) * SM_STRIDE + bcol) * 4);
    }

    auto issue = [&](int it, int stage) {
        const int kb = it * BK;
        const uint32_t base = smb + (uint32_t)stage * (SMG_STAGE * 4);
#pragma unroll
        for (int jj = 0; jj < 4; jj++) {
            int lin = t + jj * 256;
            int row = lin >> 3, k4 = (lin & 7) * 4;
            CP_ASYNC16(base + (uint32_t)(row * SM_STRIDE + k4) * 4,
                       &Ag[(size_t)row * DMODEL + kb + k4]);
        }
#pragma unroll
        for (int jj = 0; jj < 8; jj++) {
            int lin = t + jj * 256;
            int row = lin >> 3, k4 = (lin & 7) * 4;
            CP_ASYNC16(base + (uint32_t)(SMG_A + row * SM_STRIDE + k4) * 4,
                       &Bg[(size_t)row * DMODEL + kb + k4]);
        }
        CP_COMMIT();
    };

    const int NITER = DMODEL / BK;    // 32
    issue(0, 0);

    for (int it = 0; it < NITER; it++) {
        if (it + 1 < NITER) { issue(it + 1, (it + 1) & 1); CP_WAIT1(); }
        else                { CP_WAIT0(); }
        __syncthreads();

        const uint32_t sbase = smb + (uint32_t)(it & 1) * (SMG_STAGE * 4);
#pragma unroll
        for (int ks = 0; ks < 4; ks++) {
            const uint32_t ko = (uint32_t)(ks * 32);   // 8 floats
            uint32_t af[4][4];
#pragma unroll
            for (int mt = 0; mt < 4; mt++)
                ldsm_x4(af[mt][0], af[mt][1], af[mt][2], af[mt][3], sbase + aoff[mt] + ko);
#pragma unroll
            for (int p = 0; p < 4; p++) {
                uint32_t bb0, bb1, bb2, bb3;
                ldsm_x4(bb0, bb1, bb2, bb3, sbase + boff[p] + ko);
#pragma unroll
                for (int mt = 0; mt < 4; mt++) {
                    mma_tf32(acc[mt][2*p][0], acc[mt][2*p][1], acc[mt][2*p][2], acc[mt][2*p][3],
                             af[mt][0], af[mt][1], af[mt][2], af[mt][3], bb0, bb1);
                    mma_tf32(acc[mt][2*p+1][0], acc[mt][2*p+1][1], acc[mt][2*p+1][2], acc[mt][2*p+1][3],
                             af[mt][0], af[mt][1], af[mt][2], af[mt][3], bb2, bb3);
                }
            }
        }
        __syncthreads();
    }

    // epilogue
#pragma unroll
    for (int mt = 0; mt < 4; mt++) {
#pragma unroll
        for (int nt = 0; nt < 8; nt++) {
            const int row = bm + wm * 64 + mt * 16 + g;
            const int col = bn + wn * 64 + nt * 8 + j * 2;
            const float bz0 = __ldg(&bias[col]);
            const float bz1 = __ldg(&bias[col + 1]);
            float r00 = acc[mt][nt][0] + bz0, r01 = acc[mt][nt][1] + bz1;
            float r10 = acc[mt][nt][2] + bz0, r11 = acc[mt][nt][3] + bz1;
            if (roundC) {
                const float sc = (col < DMODEL) ? QSCALE : 1.0f;  // pre-scale Q for attention
                r00 = rna_tf32(r00 * sc); r01 = rna_tf32(r01 * sc);
                r10 = rna_tf32(r10 * sc); r11 = rna_tf32(r11 * sc);
            }
            *(float2*)&C[(size_t)row * Ntot + col] = make_float2(r00, r01);
            *(float2*)&C[(size_t)(row + 8) * Ntot + col] = make_float2(r10, r11);
        }
    }
}

// ============================================================================
// Tensor-core flash attention, log2-domain softmax, ldmatrix fragments.
// CTA = 256 q-rows, 8 warps x 32 rows (mt=2). cp.async double-buffered K/V.
// ============================================================================
#define ABR 256
#define ABC 64
#define AST 68
#define VST 72
#define OFF_Q  0
#define OFF_K0 17408
#define OFF_V0 21760
#define OFF_K1 26368
#define OFF_V1 30720
#define OFF_P  35328
#define OFF_CP 52736            // cpen[2][64]
#define ATTN_SMEM ((52736 + 128) * 4)   // 211456 bytes

__global__ __launch_bounds__(256, 1) void attn_mma(const float* __restrict__ mask)
{
    extern __shared__ float sm[];
    const uint32_t smb = smem_u32(sm);
    float* Psm = sm + OFF_P;

    const int t = threadIdx.x, w = t >> 5, lane = t & 31;
    const int g = lane >> 2, j = lane & 3;
    const int bh = blockIdx.y, b = bh >> 4, h = bh & 15;
    const int q0 = blockIdx.x * ABR;

    const float* Qg = g_QKV + (size_t)b * SEQ * NQKV + h * HD;
    const float* Kg = Qg + DMODEL;
    const float* Vg = Qg + 2 * DMODEL;

    // Q tile [256 x 64] via cp.async (pre-scaled + tf32-rounded upstream)
#pragma unroll
    for (int i = 0; i < 16; i++) {
        int lin = t + i * 256;
        int r = lin >> 4, c4 = (lin & 15) * 4;
        CP_ASYNC16(smb + (uint32_t)(OFF_Q + r * AST + c4) * 4,
                   &Qg[(size_t)(q0 + r) * NQKV + c4]);
    }
    CP_COMMIT();

    auto issue_kv = [&](int kb, int s) {
        const int c0 = kb * ABC;
        const uint32_t kbase = smb + (uint32_t)(s ? OFF_K1 : OFF_K0) * 4;
        const uint32_t vbase = smb + (uint32_t)(s ? OFF_V1 : OFF_V0) * 4;
#pragma unroll
        for (int i = 0; i < 4; i++) {
            int lin = t + i * 256;
            int r = lin >> 4, c4 = (lin & 15) * 4;
            CP_ASYNC16(kbase + (uint32_t)(r * AST + c4) * 4,
                       &Kg[(size_t)(c0 + r) * NQKV + c4]);
            CP_ASYNC16(vbase + (uint32_t)(r * VST + c4) * 4,
                       &Vg[(size_t)(c0 + r) * NQKV + c4]);
        }
        if (t < ABC)
            sm[OFF_CP + s * 64 + t] = -1e6f * L2E * (1.0f - mask[b * SEQ + c0 + t]);
        CP_COMMIT();
    };

    issue_kv(0, 0);

    const int rb = w * 32;
    // ldmatrix offsets
    uint32_t qoff[2], koff[4], poff[2];
    {
        const int arow = lane & 15, acol = (lane >> 4) * 4;
#pragma unroll
        for (int mt = 0; mt < 2; mt++) {
            qoff[mt] = (uint32_t)((OFF_Q + (rb + mt * 16 + arow) * AST + acol) * 4);
            poff[mt] = (uint32_t)((OFF_P + (rb + mt * 16 + arow) * AST + acol) * 4);
        }
        const int brow = ((lane >> 4) & 1) * 8 + (lane & 7);
        const int bcol = ((lane >> 3) & 1) * 4;
#pragma unroll
        for (int p = 0; p < 4; p++)
            koff[p] = (uint32_t)(((p * 16 + brow) * AST + bcol) * 4);
    }

    float mst[2][2] = {{-1e30f, -1e30f}, {-1e30f, -1e30f}};
    float lst[2][2] = {{0.0f, 0.0f}, {0.0f, 0.0f}};
    float o[2][8][4];
#pragma unroll
    for (int mt = 0; mt < 2; mt++)
#pragma unroll
        for (int nt = 0; nt < 8; nt++)
#pragma unroll
            for (int r = 0; r < 4; r++) o[mt][nt][r] = 0.0f;

    const int NB = SEQ / ABC;        // 32
    for (int kb = 0; kb < NB; kb++) {
        const int cur = kb & 1;
        if (kb + 1 < NB) { issue_kv(kb + 1, cur ^ 1); CP_WAIT1(); }
        else             { CP_WAIT0(); }
        __syncthreads();

        const uint32_t kstage = smb + (uint32_t)(cur ? OFF_K1 : OFF_K0) * 4;
        const float* Vsm = sm + (cur ? OFF_V1 : OFF_V0);
        const float* cp  = sm + OFF_CP + cur * 64;

        // ---- S = Q' K^T (log2 units) ----
        float sacc[2][8][4];
#pragma unroll
        for (int mt = 0; mt < 2; mt++)
#pragma unroll
            for (int nt = 0; nt < 8; nt++)
#pragma unroll
                for (int r = 0; r < 4; r++) sacc[mt][nt][r] = 0.0f;

#pragma unroll
        for (int ks = 0; ks < 8; ks++) {
            const uint32_t ko = (uint32_t)(ks * 32);
            uint32_t af[2][4];
#pragma unroll
            for (int mt = 0; mt < 2; mt++)
                ldsm_x4(af[mt][0], af[mt][1], af[mt][2], af[mt][3], smb + qoff[mt] + ko);
#pragma unroll
            for (int p = 0; p < 4; p++) {
                uint32_t b0, b1, b2, b3;
                ldsm_x4(b0, b1, b2, b3, kstage + koff[p] + ko);
#pragma unroll
                for (int mt = 0; mt < 2; mt++) {
                    mma_tf32(sacc[mt][2*p][0], sacc[mt][2*p][1], sacc[mt][2*p][2], sacc[mt][2*p][3],
                             af[mt][0], af[mt][1], af[mt][2], af[mt][3], b0, b1);
                    mma_tf32(sacc[mt][2*p+1][0], sacc[mt][2*p+1][1], sacc[mt][2*p+1][2], sacc[mt][2*p+1][3],
                             af[mt][0], af[mt][1], af[mt][2], af[mt][3], b2, b3);
                }
            }
        }

        // ---- softmax (log2 domain, online max) ----
#pragma unroll
        for (int mt = 0; mt < 2; mt++) {
            float mx0 = -1e30f, mx1 = -1e30f;
#pragma unroll
            for (int nt = 0; nt < 8; nt++) {
                const float p0 = cp[nt * 8 + 2 * j], p1 = cp[nt * 8 + 2 * j + 1];
                sacc[mt][nt][0] += p0;
                sacc[mt][nt][1] += p1;
                sacc[mt][nt][2] += p0;
                sacc[mt][nt][3] += p1;
                mx0 = fmaxf(mx0, fmaxf(sacc[mt][nt][0], sacc[mt][nt][1]));
                mx1 = fmaxf(mx1, fmaxf(sacc[mt][nt][2], sacc[mt][nt][3]));
            }
            mx0 = fmaxf(mx0, __shfl_xor_sync(0xffffffffu, mx0, 1));
            mx0 = fmaxf(mx0, __shfl_xor_sync(0xffffffffu, mx0, 2));
            mx1 = fmaxf(mx1, __shfl_xor_sync(0xffffffffu, mx1, 1));
            mx1 = fmaxf(mx1, __shfl_xor_sync(0xffffffffu, mx1, 2));
            const float mn0 = fmaxf(mst[mt][0], mx0), mn1 = fmaxf(mst[mt][1], mx1);
            const float al0 = ex2(mst[mt][0] - mn0);
            const float al1 = ex2(mst[mt][1] - mn1);

            float s0 = 0.0f, s1 = 0.0f;
#pragma unroll
            for (int nt = 0; nt < 8; nt++) {
                float p00 = rna_tf32(ex2(sacc[mt][nt][0] - mn0));
                float p01 = rna_tf32(ex2(sacc[mt][nt][1] - mn0));
                float p10 = rna_tf32(ex2(sacc[mt][nt][2] - mn1));
                float p11 = rna_tf32(ex2(sacc[mt][nt][3] - mn1));
                s0 += p00 + p01;
                s1 += p10 + p11;
                o[mt][nt][0] *= al0; o[mt][nt][1] *= al0;
                o[mt][nt][2] *= al1; o[mt][nt][3] *= al1;
                float* pr = &Psm[(rb + mt * 16 + g) * AST + nt * 8 + 2 * j];
                *(float2*)pr = make_float2(p00, p01);
                *(float2*)(pr + 8 * AST) = make_float2(p10, p11);
            }
            s0 += __shfl_xor_sync(0xffffffffu, s0, 1);
            s0 += __shfl_xor_sync(0xffffffffu, s0, 2);
            s1 += __shfl_xor_sync(0xffffffffu, s1, 1);
            s1 += __shfl_xor_sync(0xffffffffu, s1, 2);
            lst[mt][0] = lst[mt][0] * al0 + s0;
            lst[mt][1] = lst[mt][1] * al1 + s1;
            mst[mt][0] = mn0; mst[mt][1] = mn1;
        }
        __syncthreads();

        // ---- O += P V ----
#pragma unroll
        for (int ks = 0; ks < 8; ks++) {
            const uint32_t ko = (uint32_t)(ks * 32);
            const int k0 = ks * 8;
            uint32_t af[2][4];
#pragma unroll
            for (int mt = 0; mt < 2; mt++)
                ldsm_x4(af[mt][0], af[mt][1], af[mt][2], af[mt][3], smb + poff[mt] + ko);
#pragma unroll
            for (int nt = 0; nt < 8; nt++) {
                const float* br = &Vsm[(k0 + j) * VST + nt * 8 + g];
                uint32_t b0 = __float_as_uint(br[0]);
                uint32_t b1 = __float_as_uint(br[4 * VST]);
#pragma unroll
                for (int mt = 0; mt < 2; mt++)
                    mma_tf32(o[mt][nt][0], o[mt][nt][1], o[mt][nt][2], o[mt][nt][3],
                             af[mt][0], af[mt][1], af[mt][2], af[mt][3], b0, b1);
            }
        }
        __syncthreads();
    }

    // epilogue
#pragma unroll
    for (int mt = 0; mt < 2; mt++) {
        const float inv0 = 1.0f / lst[mt][0];
        const float inv1 = 1.0f / lst[mt][1];
        const size_t row0 = (size_t)(b * SEQ + q0 + rb + mt * 16 + g);
#pragma unroll
        for (int nt = 0; nt < 8; nt++) {
            const int col = h * HD + nt * 8 + 2 * j;
            float2 v0 = make_float2(rna_tf32(o[mt][nt][0] * inv0), rna_tf32(o[mt][nt][1] * inv0));
            float2 v1 = make_float2(rna_tf32(o[mt][nt][2] * inv1), rna_tf32(o[mt][nt][3] * inv1));
            *(float2*)&g_C[row0 * DMODEL + col] = v0;
            *(float2*)&g_C[(row0 + 8) * DMODEL + col] = v1;
        }
    }
}

// ============================================================================
// prep kernels
// ============================================================================
__global__ void prep_round_X(const float* __restrict__ X, float* __restrict__ out) {
    int i = blockIdx.x * blockDim.x + threadIdx.x;
    if (i < MROWS * DMODEL) out[i] = rna_tf32(X[i]);
}

__global__ void prep_transpose(const float* __restrict__ Wq, const float* __restrict__ Wk,
                               const float* __restrict__ Wv, const float* __restrict__ Wo) {
    __shared__ float tile[32][33];
    const int z = blockIdx.z;
    const float* W = (z == 0) ? Wq : (z == 1) ? Wk : (z == 2) ? Wv : Wo;
    float* Dst = (z == 3) ? g_WtO : (g_WtQKV + (size_t)z * DMODEL * DMODEL);
    const int n0 = blockIdx.x * 32, k0 = blockIdx.y * 32;
    const int tx = threadIdx.x, ty0 = threadIdx.y;
#pragma unroll
    for (int ty = ty0; ty < 32; ty += 8)
        tile[ty][tx] = rna_tf32(W[(size_t)(k0 + ty) * DMODEL + n0 + tx]);
    __syncthreads();
#pragma unroll
    for (int ty = ty0; ty < 32; ty += 8)
        Dst[(size_t)(n0 + ty) * DMODEL + k0 + tx] = tile[tx][ty];
}

__global__ void prep_bias(const float* __restrict__ bq, const float* __restrict__ bk,
                          const float* __restrict__ bv) {
    int i = blockIdx.x * blockDim.x + threadIdx.x;
    if (i < NQKV)
        g_biasQKV[i] = (i < 1024) ? bq[i] : (i < 2048) ? bk[i - 1024] : bv[i - 2048];
}

// ============================================================================
extern "C" void kernel_launch(void* const* d_in, const int* in_sizes, int n_in,
                              void* d_out, int out_size)
{
    const float* X    = (const float*)d_in[0];
    const float* mask = (const float*)d_in[1];
    const float* Wq   = (const float*)d_in[2];
    const float* bq   = (const float*)d_in[3];
    const float* Wk   = (const float*)d_in[4];
    const float* bk   = (const float*)d_in[5];
    const float* Wv   = (const float*)d_in[6];
    const float* bv   = (const float*)d_in[7];
    const float* Wo   = (const float*)d_in[8];
    const float* bo   = (const float*)d_in[9];
    float* out = (float*)d_out;

    cudaFuncSetAttribute(gemm_mma, cudaFuncAttributeMaxDynamicSharedMemorySize, GEMM_SMEM);
    cudaFuncSetAttribute(attn_mma, cudaFuncAttributeMaxDynamicSharedMemorySize, ATTN_SMEM);

    float* dA;     cudaGetSymbolAddress((void**)&dA, g_A);
    float* dQKV;   cudaGetSymbolAddress((void**)&dQKV, g_QKV);
    float* dC;     cudaGetSymbolAddress((void**)&dC, g_C);
    float* dWtQKV; cudaGetSymbolAddress((void**)&dWtQKV, g_WtQKV);
    float* dWtO;   cudaGetSymbolAddress((void**)&dWtO, g_WtO);
    float* dBias;  cudaGetSymbolAddress((void**)&dBias, g_biasQKV);

    prep_round_X<<<(MROWS * DMODEL + 255) / 256, 256>>>(X, dA);
    prep_transpose<<<dim3(32, 32, 4), dim3(32, 8)>>>(Wq, Wk, Wv, Wo);
    prep_bias<<<(NQKV + 255) / 256, 256>>>(bq, bk, bv);

    // QKV projection (Q pre-scaled by 0.125*log2e, all tf32-rounded)
    gemm_mma<<<dim3(NQKV / 256, MROWS / 128), 256, GEMM_SMEM>>>(dA, dWtQKV, dBias, dQKV, NQKV, 1);
    // tensor-core flash attention (log2-domain softmax)
    attn_mma<<<dim3(SEQ / ABR, BSZ * NH), 256, ATTN_SMEM>>>(mask);
    // output projection -> d_out
    gemm_mma<<<dim3(DMODEL / 256, MROWS / 128), 256, GEMM_SMEM>>>(dC, dWtO, bo, out, DMODEL, 0);
}

// round 12
// speedup vs baseline: 4.5014x; 1.0307x over previous
#include <cuda_runtime.h>
#include <math.h>
#include <stdint.h>

#define BSZ 2
#define SEQ 2048
#define DMODEL 1024
#define NH 16
#define HD 64
#define MROWS (BSZ * SEQ)   // 4096
#define NQKV (3 * DMODEL)   // 3072
#define L2E 1.4426950408889634f
#define QSCALE (0.125f * L2E)

// -------- scratch (device globals; no allocation allowed) --------
__device__ float g_A[MROWS * DMODEL];        // tf32-rounded X
__device__ float g_QKV[MROWS * NQKV];        // Q(pre-scaled)|K|V tf32-rounded
__device__ float g_C[MROWS * DMODEL];        // attention output (tf32-rounded)
__device__ float g_WtQKV[NQKV * DMODEL];     // transposed+rounded Wq|Wk|Wv [n][k]
__device__ float g_WtO[DMODEL * DMODEL];     // transposed+rounded Wo       [n][k]
__device__ float g_biasQKV[NQKV];

__device__ __forceinline__ float rna_tf32(float x) {
    uint32_t u;
    asm("cvt.rna.tf32.f32 %0, %1;" : "=r"(u) : "f"(x));
    return __uint_as_float(u);
}
__device__ __forceinline__ float ex2(float x) {
    float r;
    asm("ex2.approx.ftz.f32 %0, %1;" : "=f"(r) : "f"(x));
    return r;
}
__device__ __forceinline__ uint32_t smem_u32(const void* p) {
    uint32_t a;
    asm("{ .reg .u64 t; cvta.to.shared.u64 t, %1; cvt.u32.u64 %0, t; }" : "=r"(a) : "l"(p));
    return a;
}
#define CP_ASYNC16(dst, src) \
    asm volatile("cp.async.ca.shared.global [%0], [%1], 16;" :: "r"(dst), "l"(src))
#define CP_COMMIT() asm volatile("cp.async.commit_group;" ::: "memory")
#define CP_WAIT0()  asm volatile("cp.async.wait_group 0;" ::: "memory")

__device__ __forceinline__ void mma_tf32(float& c0, float& c1, float& c2, float& c3,
                                         uint32_t a0, uint32_t a1, uint32_t a2, uint32_t a3,
                                         uint32_t b0, uint32_t b1) {
    asm volatile(
        "mma.sync.aligned.m16n8k8.row.col.f32.tf32.tf32.f32 "
        "{%0,%1,%2,%3}, {%4,%5,%6,%7}, {%8,%9}, {%0,%1,%2,%3};"
        : "+f"(c0), "+f"(c1), "+f"(c2), "+f"(c3)
        : "r"(a0), "r"(a1), "r"(a2), "r"(a3), "r"(b0), "r"(b1));
}
// type-agnostic 16B-row matrix load: 4 m8n8 tiles of 32-bit data
__device__ __forceinline__ void ldsm_x4(uint32_t& r0, uint32_t& r1, uint32_t& r2, uint32_t& r3,
                                        uint32_t addr) {
    asm volatile("ldmatrix.sync.aligned.m8n8.x4.shared.b16 {%0,%1,%2,%3}, [%4];"
                 : "=r"(r0), "=r"(r1), "=r"(r2), "=r"(r3) : "r"(addr));
}

// ============================================================================
// tf32 mma.sync GEMM: C[M, Ntot] = A[M,1024] @ Bt[Ntot,1024]^T + bias
// CTA 128x128, 128 threads = 4 warps (2m x 2n), warp tile 64x64.
// 2 CTAs/SM; single __syncthreads per K-iter (issue-after-barrier pipeline).
// ============================================================================
#define BK 32
#define SM_STRIDE 36
#define SMG_A (128 * SM_STRIDE)             // 4608 floats
#define SMG_STAGE (2 * SMG_A)               // A+B = 9216 floats
#define GEMM_SMEM (2 * SMG_STAGE * 4)       // 73728 bytes

__global__ __launch_bounds__(128, 2) void gemm_mma(
    const float* __restrict__ A, const float* __restrict__ Bt,
    const float* __restrict__ bias, float* __restrict__ C, int Ntot, int roundC)
{
    extern __shared__ float sm[];
    const uint32_t smb = smem_u32(sm);
    const int t    = threadIdx.x;
    const int wid  = t >> 5;
    const int lane = t & 31;
    const int wm   = wid >> 1;     // 0..1
    const int wn   = wid & 1;      // 0..1
    const int g    = lane >> 2;
    const int j    = lane & 3;
    const int bm = blockIdx.y * 128;
    const int bn = blockIdx.x * 128;

    const float* Ag = A  + (size_t)bm * DMODEL;
    const float* Bg = Bt + (size_t)bn * DMODEL;

    float acc[4][8][4];
#pragma unroll
    for (int mt = 0; mt < 4; mt++)
#pragma unroll
        for (int nt = 0; nt < 8; nt++)
#pragma unroll
            for (int r = 0; r < 4; r++) acc[mt][nt][r] = 0.0f;

    // ldmatrix lane-address offsets (bytes within a stage)
    uint32_t aoff[4], boff[4];
    {
        const int arow = lane & 15, acol = (lane >> 4) * 4;
#pragma unroll
        for (int mt = 0; mt < 4; mt++)
            aoff[mt] = (uint32_t)(((wm * 64 + mt * 16 + arow) * SM_STRIDE + acol) * 4);
        const int brow = ((lane >> 4) & 1) * 8 + (lane & 7);
        const int bcol = ((lane >> 3) & 1) * 4;
#pragma unroll
        for (int p = 0; p < 4; p++)
            boff[p] = (uint32_t)((SMG_A + (wn * 64 + p * 16 + brow) * SM_STRIDE + bcol) * 4);
    }

    auto issue = [&](int it, int stage) {
        const int kb = it * BK;
        const uint32_t base = smb + (uint32_t)stage * (SMG_STAGE * 4);
#pragma unroll
        for (int jj = 0; jj < 8; jj++) {
            int lin = t + jj * 128;
            int row = lin >> 3, k4 = (lin & 7) * 4;
            CP_ASYNC16(base + (uint32_t)(row * SM_STRIDE + k4) * 4,
                       &Ag[(size_t)row * DMODEL + kb + k4]);
            CP_ASYNC16(base + (uint32_t)(SMG_A + row * SM_STRIDE + k4) * 4,
                       &Bg[(size_t)row * DMODEL + kb + k4]);
        }
        CP_COMMIT();
    };

    const int NITER = DMODEL / BK;    // 32
    issue(0, 0);

    for (int it = 0; it < NITER; it++) {
        CP_WAIT0();
        __syncthreads();
        if (it + 1 < NITER) issue(it + 1, (it + 1) & 1);

        const uint32_t sbase = smb + (uint32_t)(it & 1) * (SMG_STAGE * 4);
#pragma unroll
        for (int ks = 0; ks < 4; ks++) {
            const uint32_t ko = (uint32_t)(ks * 32);   // 8 floats
            uint32_t af[4][4];
#pragma unroll
            for (int mt = 0; mt < 4; mt++)
                ldsm_x4(af[mt][0], af[mt][1], af[mt][2], af[mt][3], sbase + aoff[mt] + ko);
#pragma unroll
            for (int p = 0; p < 4; p++) {
                uint32_t bb0, bb1, bb2, bb3;
                ldsm_x4(bb0, bb1, bb2, bb3, sbase + boff[p] + ko);
#pragma unroll
                for (int mt = 0; mt < 4; mt++) {
                    mma_tf32(acc[mt][2*p][0], acc[mt][2*p][1], acc[mt][2*p][2], acc[mt][2*p][3],
                             af[mt][0], af[mt][1], af[mt][2], af[mt][3], bb0, bb1);
                    mma_tf32(acc[mt][2*p+1][0], acc[mt][2*p+1][1], acc[mt][2*p+1][2], acc[mt][2*p+1][3],
                             af[mt][0], af[mt][1], af[mt][2], af[mt][3], bb2, bb3);
                }
            }
        }
    }

    // epilogue
#pragma unroll
    for (int mt = 0; mt < 4; mt++) {
#pragma unroll
        for (int nt = 0; nt < 8; nt++) {
            const int row = bm + wm * 64 + mt * 16 + g;
            const int col = bn + wn * 64 + nt * 8 + j * 2;
            const float bz0 = __ldg(&bias[col]);
            const float bz1 = __ldg(&bias[col + 1]);
            float r00 = acc[mt][nt][0] + bz0, r01 = acc[mt][nt][1] + bz1;
            float r10 = acc[mt][nt][2] + bz0, r11 = acc[mt][nt][3] + bz1;
            if (roundC) {
                const float sc = (col < DMODEL) ? QSCALE : 1.0f;  // pre-scale Q
                r00 = rna_tf32(r00 * sc); r01 = rna_tf32(r01 * sc);
                r10 = rna_tf32(r10 * sc); r11 = rna_tf32(r11 * sc);
            }
            *(float2*)&C[(size_t)row * Ntot + col] = make_float2(r00, r01);
            *(float2*)&C[(size_t)(row + 8) * Ntot + col] = make_float2(r10, r11);
        }
    }
}

// ============================================================================
// Tensor-core flash attention, log2-domain softmax, ldmatrix fragments.
// CTA = 256 q-rows, 8 warps x 32 rows. ONE __syncthreads per KV tile:
// P tile rows are warp-private, so softmax->PV needs only __syncwarp.
// ============================================================================
#define ABR 256
#define ABC 64
#define AST 68
#define VST 72
#define OFF_Q  0
#define OFF_K0 17408
#define OFF_V0 21760
#define OFF_K1 26368
#define OFF_V1 30720
#define OFF_P  35328
#define OFF_CP 52736            // cpen[2][64]
#define ATTN_SMEM ((52736 + 128) * 4)   // 211456 bytes

__global__ __launch_bounds__(256, 1) void attn_mma(const float* __restrict__ mask)
{
    extern __shared__ float sm[];
    const uint32_t smb = smem_u32(sm);
    float* Psm = sm + OFF_P;

    const int t = threadIdx.x, w = t >> 5, lane = t & 31;
    const int g = lane >> 2, j = lane & 3;
    const int bh = blockIdx.y, b = bh >> 4, h = bh & 15;
    const int q0 = blockIdx.x * ABR;

    const float* Qg = g_QKV + (size_t)b * SEQ * NQKV + h * HD;
    const float* Kg = Qg + DMODEL;
    const float* Vg = Qg + 2 * DMODEL;

    // Q tile [256 x 64] via cp.async (pre-scaled + tf32-rounded upstream)
#pragma unroll
    for (int i = 0; i < 16; i++) {
        int lin = t + i * 256;
        int r = lin >> 4, c4 = (lin & 15) * 4;
        CP_ASYNC16(smb + (uint32_t)(OFF_Q + r * AST + c4) * 4,
                   &Qg[(size_t)(q0 + r) * NQKV + c4]);
    }
    CP_COMMIT();

    auto issue_kv = [&](int kb, int s) {
        const int c0 = kb * ABC;
        const uint32_t kbase = smb + (uint32_t)(s ? OFF_K1 : OFF_K0) * 4;
        const uint32_t vbase = smb + (uint32_t)(s ? OFF_V1 : OFF_V0) * 4;
#pragma unroll
        for (int i = 0; i < 4; i++) {
            int lin = t + i * 256;
            int r = lin >> 4, c4 = (lin & 15) * 4;
            CP_ASYNC16(kbase + (uint32_t)(r * AST + c4) * 4,
                       &Kg[(size_t)(c0 + r) * NQKV + c4]);
            CP_ASYNC16(vbase + (uint32_t)(r * VST + c4) * 4,
                       &Vg[(size_t)(c0 + r) * NQKV + c4]);
        }
        if (t < ABC)
            sm[OFF_CP + s * 64 + t] = -1e6f * L2E * (1.0f - mask[b * SEQ + c0 + t]);
        CP_COMMIT();
    };

    issue_kv(0, 0);

    const int rb = w * 32;
    uint32_t qoff[2], koff[4], poff[2];
    {
        const int arow = lane & 15, acol = (lane >> 4) * 4;
#pragma unroll
        for (int mt = 0; mt < 2; mt++) {
            qoff[mt] = (uint32_t)((OFF_Q + (rb + mt * 16 + arow) * AST + acol) * 4);
            poff[mt] = (uint32_t)((OFF_P + (rb + mt * 16 + arow) * AST + acol) * 4);
        }
        const int brow = ((lane >> 4) & 1) * 8 + (lane & 7);
        const int bcol = ((lane >> 3) & 1) * 4;
#pragma unroll
        for (int p = 0; p < 4; p++)
            koff[p] = (uint32_t)(((p * 16 + brow) * AST + bcol) * 4);
    }

    float mst[2][2] = {{-1e30f, -1e30f}, {-1e30f, -1e30f}};
    float lst[2][2] = {{0.0f, 0.0f}, {0.0f, 0.0f}};
    float o[2][8][4];
#pragma unroll
    for (int mt = 0; mt < 2; mt++)
#pragma unroll
        for (int nt = 0; nt < 8; nt++)
#pragma unroll
            for (int r = 0; r < 4; r++) o[mt][nt][r] = 0.0f;

    const int NB = SEQ / ABC;        // 32
    for (int kb = 0; kb < NB; kb++) {
        const int cur = kb & 1;
        CP_WAIT0();
        __syncthreads();
        if (kb + 1 < NB) issue_kv(kb + 1, cur ^ 1);

        const uint32_t kstage = smb + (uint32_t)(cur ? OFF_K1 : OFF_K0) * 4;
        const float* Vsm = sm + (cur ? OFF_V1 : OFF_V0);
        const float* cp  = sm + OFF_CP + cur * 64;

        // ---- S = Q' K^T (log2 units) ----
        float sacc[2][8][4];
#pragma unroll
        for (int mt = 0; mt < 2; mt++)
#pragma unroll
            for (int nt = 0; nt < 8; nt++)
#pragma unroll
                for (int r = 0; r < 4; r++) sacc[mt][nt][r] = 0.0f;

#pragma unroll
        for (int ks = 0; ks < 8; ks++) {
            const uint32_t ko = (uint32_t)(ks * 32);
            uint32_t af[2][4];
#pragma unroll
            for (int mt = 0; mt < 2; mt++)
                ldsm_x4(af[mt][0], af[mt][1], af[mt][2], af[mt][3], smb + qoff[mt] + ko);
#pragma unroll
            for (int p = 0; p < 4; p++) {
                uint32_t b0, b1, b2, b3;
                ldsm_x4(b0, b1, b2, b3, kstage + koff[p] + ko);
#pragma unroll
                for (int mt = 0; mt < 2; mt++) {
                    mma_tf32(sacc[mt][2*p][0], sacc[mt][2*p][1], sacc[mt][2*p][2], sacc[mt][2*p][3],
                             af[mt][0], af[mt][1], af[mt][2], af[mt][3], b0, b1);
                    mma_tf32(sacc[mt][2*p+1][0], sacc[mt][2*p+1][1], sacc[mt][2*p+1][2], sacc[mt][2*p+1][3],
                             af[mt][0], af[mt][1], af[mt][2], af[mt][3], b2, b3);
                }
            }
        }

        // ---- softmax (log2 domain, online max) ----
#pragma unroll
        for (int mt = 0; mt < 2; mt++) {
            float mx0 = -1e30f, mx1 = -1e30f;
#pragma unroll
            for (int nt = 0; nt < 8; nt++) {
                const float p0 = cp[nt * 8 + 2 * j], p1 = cp[nt * 8 + 2 * j + 1];
                sacc[mt][nt][0] += p0;
                sacc[mt][nt][1] += p1;
                sacc[mt][nt][2] += p0;
                sacc[mt][nt][3] += p1;
                mx0 = fmaxf(mx0, fmaxf(sacc[mt][nt][0], sacc[mt][nt][1]));
                mx1 = fmaxf(mx1, fmaxf(sacc[mt][nt][2], sacc[mt][nt][3]));
            }
            mx0 = fmaxf(mx0, __shfl_xor_sync(0xffffffffu, mx0, 1));
            mx0 = fmaxf(mx0, __shfl_xor_sync(0xffffffffu, mx0, 2));
            mx1 = fmaxf(mx1, __shfl_xor_sync(0xffffffffu, mx1, 1));
            mx1 = fmaxf(mx1, __shfl_xor_sync(0xffffffffu, mx1, 2));
            const float mn0 = fmaxf(mst[mt][0], mx0), mn1 = fmaxf(mst[mt][1], mx1);
            const float al0 = ex2(mst[mt][0] - mn0);
            const float al1 = ex2(mst[mt][1] - mn1);

            float s0 = 0.0f, s1 = 0.0f;
#pragma unroll
            for (int nt = 0; nt < 8; nt++) {
                float p00 = rna_tf32(ex2(sacc[mt][nt][0] - mn0));
                float p01 = rna_tf32(ex2(sacc[mt][nt][1] - mn0));
                float p10 = rna_tf32(ex2(sacc[mt][nt][2] - mn1));
                float p11 = rna_tf32(ex2(sacc[mt][nt][3] - mn1));
                s0 += p00 + p01;
                s1 += p10 + p11;
                o[mt][nt][0] *= al0; o[mt][nt][1] *= al0;
                o[mt][nt][2] *= al1; o[mt][nt][3] *= al1;
                float* pr = &Psm[(rb + mt * 16 + g) * AST + nt * 8 + 2 * j];
                *(float2*)pr = make_float2(p00, p01);
                *(float2*)(pr + 8 * AST) = make_float2(p10, p11);
            }
            s0 += __shfl_xor_sync(0xffffffffu, s0, 1);
            s0 += __shfl_xor_sync(0xffffffffu, s0, 2);
            s1 += __shfl_xor_sync(0xffffffffu, s1, 1);
            s1 += __shfl_xor_sync(0xffffffffu, s1, 2);
            lst[mt][0] = lst[mt][0] * al0 + s0;
            lst[mt][1] = lst[mt][1] * al1 + s1;
            mst[mt][0] = mn0; mst[mt][1] = mn1;
        }
        __syncwarp();   // P rows are warp-private: warp-level visibility suffices

        // ---- O += P V ----
#pragma unroll
        for (int ks = 0; ks < 8; ks++) {
            const uint32_t ko = (uint32_t)(ks * 32);
            const int k0 = ks * 8;
            uint32_t af[2][4];
#pragma unroll
            for (int mt = 0; mt < 2; mt++)
                ldsm_x4(af[mt][0], af[mt][1], af[mt][2], af[mt][3], smb + poff[mt] + ko);
#pragma unroll
            for (int nt = 0; nt < 8; nt++) {
                const float* br = &Vsm[(k0 + j) * VST + nt * 8 + g];
                uint32_t b0 = __float_as_uint(br[0]);
                uint32_t b1 = __float_as_uint(br[4 * VST]);
#pragma unroll
                for (int mt = 0; mt < 2; mt++)
                    mma_tf32(o[mt][nt][0], o[mt][nt][1], o[mt][nt][2], o[mt][nt][3],
                             af[mt][0], af[mt][1], af[mt][2], af[mt][3], b0, b1);
            }
        }
    }

    // epilogue
#pragma unroll
    for (int mt = 0; mt < 2; mt++) {
        const float inv0 = 1.0f / lst[mt][0];
        const float inv1 = 1.0f / lst[mt][1];
        const size_t row0 = (size_t)(b * SEQ + q0 + rb + mt * 16 + g);
#pragma unroll
        for (int nt = 0; nt < 8; nt++) {
            const int col = h * HD + nt * 8 + 2 * j;
            float2 v0 = make_float2(rna_tf32(o[mt][nt][0] * inv0), rna_tf32(o[mt][nt][1] * inv0));
            float2 v1 = make_float2(rna_tf32(o[mt][nt][2] * inv1), rna_tf32(o[mt][nt][3] * inv1));
            *(float2*)&g_C[row0 * DMODEL + col] = v0;
            *(float2*)&g_C[(row0 + 8) * DMODEL + col] = v1;
        }
    }
}

// ============================================================================
// prep kernels
// ============================================================================
__global__ void prep_round_X(const float* __restrict__ X, float* __restrict__ out) {
    int i = blockIdx.x * blockDim.x + threadIdx.x;
    if (i < MROWS * DMODEL) out[i] = rna_tf32(X[i]);
}

__global__ void prep_transpose(const float* __restrict__ Wq, const float* __restrict__ Wk,
                               const float* __restrict__ Wv, const float* __restrict__ Wo) {
    __shared__ float tile[32][33];
    const int z = blockIdx.z;
    const float* W = (z == 0) ? Wq : (z == 1) ? Wk : (z == 2) ? Wv : Wo;
    float* Dst = (z == 3) ? g_WtO : (g_WtQKV + (size_t)z * DMODEL * DMODEL);
    const int n0 = blockIdx.x * 32, k0 = blockIdx.y * 32;
    const int tx = threadIdx.x, ty0 = threadIdx.y;
#pragma unroll
    for (int ty = ty0; ty < 32; ty += 8)
        tile[ty][tx] = rna_tf32(W[(size_t)(k0 + ty) * DMODEL + n0 + tx]);
    __syncthreads();
#pragma unroll
    for (int ty = ty0; ty < 32; ty += 8)
        Dst[(size_t)(n0 + ty) * DMODEL + k0 + tx] = tile[tx][ty];
}

__global__ void prep_bias(const float* __restrict__ bq, const float* __restrict__ bk,
                          const float* __restrict__ bv) {
    int i = blockIdx.x * blockDim.x + threadIdx.x;
    if (i < NQKV)
        g_biasQKV[i] = (i < 1024) ? bq[i] : (i < 2048) ? bk[i - 1024] : bv[i - 2048];
}

// ============================================================================
extern "C" void kernel_launch(void* const* d_in, const int* in_sizes, int n_in,
                              void* d_out, int out_size)
{
    const float* X    = (const float*)d_in[0];
    const float* mask = (const float*)d_in[1];
    const float* Wq   = (const float*)d_in[2];
    const float* bq   = (const float*)d_in[3];
    const float* Wk   = (const float*)d_in[4];
    const float* bk   = (const float*)d_in[5];
    const float* Wv   = (const float*)d_in[6];
    const float* bv   = (const float*)d_in[7];
    const float* Wo   = (const float*)d_in[8];
    const float* bo   = (const float*)d_in[9];
    float* out = (float*)d_out;

    cudaFuncSetAttribute(gemm_mma, cudaFuncAttributeMaxDynamicSharedMemorySize, GEMM_SMEM);
    cudaFuncSetAttribute(attn_mma, cudaFuncAttributeMaxDynamicSharedMemorySize, ATTN_SMEM);

    float* dA;     cudaGetSymbolAddress((void**)&dA, g_A);
    float* dQKV;   cudaGetSymbolAddress((void**)&dQKV, g_QKV);
    float* dC;     cudaGetSymbolAddress((void**)&dC, g_C);
    float* dWtQKV; cudaGetSymbolAddress((void**)&dWtQKV, g_WtQKV);
    float* dWtO;   cudaGetSymbolAddress((void**)&dWtO, g_WtO);
    float* dBias;  cudaGetSymbolAddress((void**)&dBias, g_biasQKV);

    prep_round_X<<<(MROWS * DMODEL + 255) / 256, 256>>>(X, dA);
    prep_transpose<<<dim3(32, 32, 4), dim3(32, 8)>>>(Wq, Wk, Wv, Wo);
    prep_bias<<<(NQKV + 255) / 256, 256>>>(bq, bk, bv);

    // QKV projection (Q pre-scaled by 0.125*log2e, all tf32-rounded)
    gemm_mma<<<dim3(NQKV / 128, MROWS / 128), 128, GEMM_SMEM>>>(dA, dWtQKV, dBias, dQKV, NQKV, 1);
    // tensor-core flash attention (log2-domain softmax)
    attn_mma<<<dim3(SEQ / ABR, BSZ * NH), 256, ATTN_SMEM>>>(mask);
    // output projection -> d_out
    gemm_mma<<<dim3(DMODEL / 128, MROWS / 128), 128, GEMM_SMEM>>>(dC, dWtO, bo, out, DMODEL, 0);
}

// round 13
// speedup vs baseline: 4.5747x; 1.0163x over previous
#include <cuda_runtime.h>
#include <math.h>
#include <stdint.h>

#define BSZ 2
#define SEQ 2048
#define DMODEL 1024
#define NH 16
#define HD 64
#define MROWS (BSZ * SEQ)   // 4096
#define NQKV (3 * DMODEL)   // 3072
#define L2E 1.4426950408889634f
#define QSCALE (0.125f * L2E)

// -------- scratch (device globals; no allocation allowed) --------
__device__ float g_A[MROWS * DMODEL];        // tf32-rounded X
__device__ float g_QKV[MROWS * NQKV];        // Q(pre-scaled)|K|V tf32-rounded
__device__ float g_C[MROWS * DMODEL];        // attention output (tf32-rounded)
__device__ float g_WtQKV[NQKV * DMODEL];     // transposed+rounded Wq|Wk|Wv [n][k]
__device__ float g_WtO[DMODEL * DMODEL];     // transposed+rounded Wo       [n][k]
__device__ float g_biasQKV[NQKV];

__device__ __forceinline__ float rna_tf32(float x) {
    uint32_t u;
    asm("cvt.rna.tf32.f32 %0, %1;" : "=r"(u) : "f"(x));
    return __uint_as_float(u);
}
__device__ __forceinline__ float ex2(float x) {
    float r;
    asm("ex2.approx.ftz.f32 %0, %1;" : "=f"(r) : "f"(x));
    return r;
}
__device__ __forceinline__ uint32_t smem_u32(const void* p) {
    uint32_t a;
    asm("{ .reg .u64 t; cvta.to.shared.u64 t, %1; cvt.u32.u64 %0, t; }" : "=r"(a) : "l"(p));
    return a;
}
#define CP_ASYNC16(dst, src) \
    asm volatile("cp.async.ca.shared.global [%0], [%1], 16;" :: "r"(dst), "l"(src))
#define CP_COMMIT() asm volatile("cp.async.commit_group;" ::: "memory")
#define CP_WAIT0()  asm volatile("cp.async.wait_group 0;" ::: "memory")

__device__ __forceinline__ void mma_tf32(float& c0, float& c1, float& c2, float& c3,
                                         uint32_t a0, uint32_t a1, uint32_t a2, uint32_t a3,
                                         uint32_t b0, uint32_t b1) {
    asm volatile(
        "mma.sync.aligned.m16n8k8.row.col.f32.tf32.tf32.f32 "
        "{%0,%1,%2,%3}, {%4,%5,%6,%7}, {%8,%9}, {%0,%1,%2,%3};"
        : "+f"(c0), "+f"(c1), "+f"(c2), "+f"(c3)
        : "r"(a0), "r"(a1), "r"(a2), "r"(a3), "r"(b0), "r"(b1));
}
__device__ __forceinline__ void ldsm_x4(uint32_t& r0, uint32_t& r1, uint32_t& r2, uint32_t& r3,
                                        uint32_t addr) {
    asm volatile("ldmatrix.sync.aligned.m8n8.x4.shared.b16 {%0,%1,%2,%3}, [%4];"
                 : "=r"(r0), "=r"(r1), "=r"(r2), "=r"(r3) : "r"(addr));
}

// ============================================================================
// tf32 mma.sync GEMM (unchanged from R12): CTA 128x128, 128 thr, 2 CTAs/SM.
// ============================================================================
#define BK 32
#define SM_STRIDE 36
#define SMG_A (128 * SM_STRIDE)
#define SMG_STAGE (2 * SMG_A)
#define GEMM_SMEM (2 * SMG_STAGE * 4)

__global__ __launch_bounds__(128, 2) void gemm_mma(
    const float* __restrict__ A, const float* __restrict__ Bt,
    const float* __restrict__ bias, float* __restrict__ C, int Ntot, int roundC)
{
    extern __shared__ float sm[];
    const uint32_t smb = smem_u32(sm);
    const int t    = threadIdx.x;
    const int wid  = t >> 5;
    const int lane = t & 31;
    const int wm   = wid >> 1;
    const int wn   = wid & 1;
    const int g    = lane >> 2;
    const int j    = lane & 3;
    const int bm = blockIdx.y * 128;
    const int bn = blockIdx.x * 128;

    const float* Ag = A  + (size_t)bm * DMODEL;
    const float* Bg = Bt + (size_t)bn * DMODEL;

    float acc[4][8][4];
#pragma unroll
    for (int mt = 0; mt < 4; mt++)
#pragma unroll
        for (int nt = 0; nt < 8; nt++)
#pragma unroll
            for (int r = 0; r < 4; r++) acc[mt][nt][r] = 0.0f;

    uint32_t aoff[4], boff[4];
    {
        const int arow = lane & 15, acol = (lane >> 4) * 4;
#pragma unroll
        for (int mt = 0; mt < 4; mt++)
            aoff[mt] = (uint32_t)(((wm * 64 + mt * 16 + arow) * SM_STRIDE + acol) * 4);
        const int brow = ((lane >> 4) & 1) * 8 + (lane & 7);
        const int bcol = ((lane >> 3) & 1) * 4;
#pragma unroll
        for (int p = 0; p < 4; p++)
            boff[p] = (uint32_t)((SMG_A + (wn * 64 + p * 16 + brow) * SM_STRIDE + bcol) * 4);
    }

    auto issue = [&](int it, int stage) {
        const int kb = it * BK;
        const uint32_t base = smb + (uint32_t)stage * (SMG_STAGE * 4);
#pragma unroll
        for (int jj = 0; jj < 8; jj++) {
            int lin = t + jj * 128;
            int row = lin >> 3, k4 = (lin & 7) * 4;
            CP_ASYNC16(base + (uint32_t)(row * SM_STRIDE + k4) * 4,
                       &Ag[(size_t)row * DMODEL + kb + k4]);
            CP_ASYNC16(base + (uint32_t)(SMG_A + row * SM_STRIDE + k4) * 4,
                       &Bg[(size_t)row * DMODEL + kb + k4]);
        }
        CP_COMMIT();
    };

    const int NITER = DMODEL / BK;
    issue(0, 0);

    for (int it = 0; it < NITER; it++) {
        CP_WAIT0();
        __syncthreads();
        if (it + 1 < NITER) issue(it + 1, (it + 1) & 1);

        const uint32_t sbase = smb + (uint32_t)(it & 1) * (SMG_STAGE * 4);
#pragma unroll
        for (int ks = 0; ks < 4; ks++) {
            const uint32_t ko = (uint32_t)(ks * 32);
            uint32_t af[4][4];
#pragma unroll
            for (int mt = 0; mt < 4; mt++)
                ldsm_x4(af[mt][0], af[mt][1], af[mt][2], af[mt][3], sbase + aoff[mt] + ko);
#pragma unroll
            for (int p = 0; p < 4; p++) {
                uint32_t bb0, bb1, bb2, bb3;
                ldsm_x4(bb0, bb1, bb2, bb3, sbase + boff[p] + ko);
#pragma unroll
                for (int mt = 0; mt < 4; mt++) {
                    mma_tf32(acc[mt][2*p][0], acc[mt][2*p][1], acc[mt][2*p][2], acc[mt][2*p][3],
                             af[mt][0], af[mt][1], af[mt][2], af[mt][3], bb0, bb1);
                    mma_tf32(acc[mt][2*p+1][0], acc[mt][2*p+1][1], acc[mt][2*p+1][2], acc[mt][2*p+1][3],
                             af[mt][0], af[mt][1], af[mt][2], af[mt][3], bb2, bb3);
                }
            }
        }
    }

#pragma unroll
    for (int mt = 0; mt < 4; mt++) {
#pragma unroll
        for (int nt = 0; nt < 8; nt++) {
            const int row = bm + wm * 64 + mt * 16 + g;
            const int col = bn + wn * 64 + nt * 8 + j * 2;
            const float bz0 = __ldg(&bias[col]);
            const float bz1 = __ldg(&bias[col + 1]);
            float r00 = acc[mt][nt][0] + bz0, r01 = acc[mt][nt][1] + bz1;
            float r10 = acc[mt][nt][2] + bz0, r11 = acc[mt][nt][3] + bz1;
            if (roundC) {
                const float sc = (col < DMODEL) ? QSCALE : 1.0f;
                r00 = rna_tf32(r00 * sc); r01 = rna_tf32(r01 * sc);
                r10 = rna_tf32(r10 * sc); r11 = rna_tf32(r11 * sc);
            }
            *(float2*)&C[(size_t)row * Ntot + col] = make_float2(r00, r01);
            *(float2*)&C[(size_t)(row + 8) * Ntot + col] = make_float2(r10, r11);
        }
    }
}

// ============================================================================
// Tensor-core flash attention with ones-augmented V:
// V col 64 = 1 (cols 65-71 = 0) -> PV MMA tile nt=8 accumulates l = sum(p)
// with identical arithmetic to the numerator. P stored raw fp32 (no CVT):
// HW tf32-truncation hits numerator and denominator identically.
// ============================================================================
#define ABR 256
#define ABC 64
#define AST 68
#define VST 72
#define OFF_Q  0
#define OFF_K0 17408
#define OFF_V0 21760
#define OFF_K1 26368
#define OFF_V1 30720
#define OFF_P  35328
#define OFF_CP 52736
#define ATTN_SMEM ((52736 + 128) * 4)

__global__ __launch_bounds__(256, 1) void attn_mma(const float* __restrict__ mask)
{
    extern __shared__ float sm[];
    const uint32_t smb = smem_u32(sm);
    float* Psm = sm + OFF_P;

    const int t = threadIdx.x, w = t >> 5, lane = t & 31;
    const int g = lane >> 2, j = lane & 3;
    const int bh = blockIdx.y, b = bh >> 4, h = bh & 15;
    const int q0 = blockIdx.x * ABR;

    const float* Qg = g_QKV + (size_t)b * SEQ * NQKV + h * HD;
    const float* Kg = Qg + DMODEL;
    const float* Vg = Qg + 2 * DMODEL;

#pragma unroll
    for (int i = 0; i < 16; i++) {
        int lin = t + i * 256;
        int r = lin >> 4, c4 = (lin & 15) * 4;
        CP_ASYNC16(smb + (uint32_t)(OFF_Q + r * AST + c4) * 4,
                   &Qg[(size_t)(q0 + r) * NQKV + c4]);
    }
    CP_COMMIT();

    // ones column init (once; cp.async only ever writes cols 0..63)
    if (t < ABC) {
        float* v0 = sm + OFF_V0 + t * VST;
        float* v1 = sm + OFF_V1 + t * VST;
        *(float4*)(v0 + 64) = make_float4(1.0f, 0.0f, 0.0f, 0.0f);
        *(float4*)(v0 + 68) = make_float4(0.0f, 0.0f, 0.0f, 0.0f);
        *(float4*)(v1 + 64) = make_float4(1.0f, 0.0f, 0.0f, 0.0f);
        *(float4*)(v1 + 68) = make_float4(0.0f, 0.0f, 0.0f, 0.0f);
    }

    auto issue_kv = [&](int kb, int s) {
        const int c0 = kb * ABC;
        const uint32_t kbase = smb + (uint32_t)(s ? OFF_K1 : OFF_K0) * 4;
        const uint32_t vbase = smb + (uint32_t)(s ? OFF_V1 : OFF_V0) * 4;
#pragma unroll
        for (int i = 0; i < 4; i++) {
            int lin = t + i * 256;
            int r = lin >> 4, c4 = (lin & 15) * 4;
            CP_ASYNC16(kbase + (uint32_t)(r * AST + c4) * 4,
                       &Kg[(size_t)(c0 + r) * NQKV + c4]);
            CP_ASYNC16(vbase + (uint32_t)(r * VST + c4) * 4,
                       &Vg[(size_t)(c0 + r) * NQKV + c4]);
        }
        if (t < ABC)
            sm[OFF_CP + s * 64 + t] = -1e6f * L2E * (1.0f - mask[b * SEQ + c0 + t]);
        CP_COMMIT();
    };

    issue_kv(0, 0);

    const int rb = w * 32;
    uint32_t qoff[2], koff[4], poff[2];
    {
        const int arow = lane & 15, acol = (lane >> 4) * 4;
#pragma unroll
        for (int mt = 0; mt < 2; mt++) {
            qoff[mt] = (uint32_t)((OFF_Q + (rb + mt * 16 + arow) * AST + acol) * 4);
            poff[mt] = (uint32_t)((OFF_P + (rb + mt * 16 + arow) * AST + acol) * 4);
        }
        const int brow = ((lane >> 4) & 1) * 8 + (lane & 7);
        const int bcol = ((lane >> 3) & 1) * 4;
#pragma unroll
        for (int p = 0; p < 4; p++)
            koff[p] = (uint32_t)(((p * 16 + brow) * AST + bcol) * 4);
    }

    float mst[2][2] = {{-1e30f, -1e30f}, {-1e30f, -1e30f}};
    float o[2][9][4];     // nt=8 tile: col 0 (j=0) accumulates l
#pragma unroll
    for (int mt = 0; mt < 2; mt++)
#pragma unroll
        for (int nt = 0; nt < 9; nt++)
#pragma unroll
            for (int r = 0; r < 4; r++) o[mt][nt][r] = 0.0f;

    const int NB = SEQ / ABC;
    for (int kb = 0; kb < NB; kb++) {
        const int cur = kb & 1;
        CP_WAIT0();
        __syncthreads();
        if (kb + 1 < NB) issue_kv(kb + 1, cur ^ 1);

        const uint32_t kstage = smb + (uint32_t)(cur ? OFF_K1 : OFF_K0) * 4;
        const float* Vsm = sm + (cur ? OFF_V1 : OFF_V0);
        const float* cp  = sm + OFF_CP + cur * 64;

        // ---- S = Q' K^T (log2 units) ----
        float sacc[2][8][4];
#pragma unroll
        for (int mt = 0; mt < 2; mt++)
#pragma unroll
            for (int nt = 0; nt < 8; nt++)
#pragma unroll
                for (int r = 0; r < 4; r++) sacc[mt][nt][r] = 0.0f;

#pragma unroll
        for (int ks = 0; ks < 8; ks++) {
            const uint32_t ko = (uint32_t)(ks * 32);
            uint32_t af[2][4];
#pragma unroll
            for (int mt = 0; mt < 2; mt++)
                ldsm_x4(af[mt][0], af[mt][1], af[mt][2], af[mt][3], smb + qoff[mt] + ko);
#pragma unroll
            for (int p = 0; p < 4; p++) {
                uint32_t b0, b1, b2, b3;
                ldsm_x4(b0, b1, b2, b3, kstage + koff[p] + ko);
#pragma unroll
                for (int mt = 0; mt < 2; mt++) {
                    mma_tf32(sacc[mt][2*p][0], sacc[mt][2*p][1], sacc[mt][2*p][2], sacc[mt][2*p][3],
                             af[mt][0], af[mt][1], af[mt][2], af[mt][3], b0, b1);
                    mma_tf32(sacc[mt][2*p+1][0], sacc[mt][2*p+1][1], sacc[mt][2*p+1][2], sacc[mt][2*p+1][3],
                             af[mt][0], af[mt][1], af[mt][2], af[mt][3], b2, b3);
                }
            }
        }

        // ---- softmax: max + exp only (l comes from the PV MMA) ----
#pragma unroll
        for (int mt = 0; mt < 2; mt++) {
            float mx0 = -1e30f, mx1 = -1e30f;
#pragma unroll
            for (int nt = 0; nt < 8; nt++) {
                const float p0 = cp[nt * 8 + 2 * j], p1 = cp[nt * 8 + 2 * j + 1];
                sacc[mt][nt][0] += p0;
                sacc[mt][nt][1] += p1;
                sacc[mt][nt][2] += p0;
                sacc[mt][nt][3] += p1;
                mx0 = fmaxf(mx0, fmaxf(sacc[mt][nt][0], sacc[mt][nt][1]));
                mx1 = fmaxf(mx1, fmaxf(sacc[mt][nt][2], sacc[mt][nt][3]));
            }
            mx0 = fmaxf(mx0, __shfl_xor_sync(0xffffffffu, mx0, 1));
            mx0 = fmaxf(mx0, __shfl_xor_sync(0xffffffffu, mx0, 2));
            mx1 = fmaxf(mx1, __shfl_xor_sync(0xffffffffu, mx1, 1));
            mx1 = fmaxf(mx1, __shfl_xor_sync(0xffffffffu, mx1, 2));
            const float mn0 = fmaxf(mst[mt][0], mx0), mn1 = fmaxf(mst[mt][1], mx1);
            const float al0 = ex2(mst[mt][0] - mn0);
            const float al1 = ex2(mst[mt][1] - mn1);
            mst[mt][0] = mn0; mst[mt][1] = mn1;

#pragma unroll
            for (int nt = 0; nt < 9; nt++) {
                o[mt][nt][0] *= al0; o[mt][nt][1] *= al0;
                o[mt][nt][2] *= al1; o[mt][nt][3] *= al1;
            }
#pragma unroll
            for (int nt = 0; nt < 8; nt++) {
                float p00 = ex2(sacc[mt][nt][0] - mn0);
                float p01 = ex2(sacc[mt][nt][1] - mn0);
                float p10 = ex2(sacc[mt][nt][2] - mn1);
                float p11 = ex2(sacc[mt][nt][3] - mn1);
                float* pr = &Psm[(rb + mt * 16 + g) * AST + nt * 8 + 2 * j];
                *(float2*)pr = make_float2(p00, p01);
                *(float2*)(pr + 8 * AST) = make_float2(p10, p11);
            }
        }
        __syncwarp();   // P rows are warp-private

        // ---- [O | l] += P [V | 1] ----
#pragma unroll
        for (int ks = 0; ks < 8; ks++) {
            const uint32_t ko = (uint32_t)(ks * 32);
            const int k0 = ks * 8;
            uint32_t af[2][4];
#pragma unroll
            for (int mt = 0; mt < 2; mt++)
                ldsm_x4(af[mt][0], af[mt][1], af[mt][2], af[mt][3], smb + poff[mt] + ko);
#pragma unroll
            for (int nt = 0; nt < 9; nt++) {
                const float* br = &Vsm[(k0 + j) * VST + nt * 8 + g];
                uint32_t b0 = __float_as_uint(br[0]);
                uint32_t b1 = __float_as_uint(br[4 * VST]);
#pragma unroll
                for (int mt = 0; mt < 2; mt++)
                    mma_tf32(o[mt][nt][0], o[mt][nt][1], o[mt][nt][2], o[mt][nt][3],
                             af[mt][0], af[mt][1], af[mt][2], af[mt][3], b0, b1);
            }
        }
    }

    // epilogue: l lives in o[mt][8][0]/[2] of j=0 threads -> broadcast in quad
#pragma unroll
    for (int mt = 0; mt < 2; mt++) {
        const float l0 = __shfl_sync(0xffffffffu, o[mt][8][0], lane & 28);
        const float l1 = __shfl_sync(0xffffffffu, o[mt][8][2], lane & 28);
        const float inv0 = 1.0f / l0;
        const float inv1 = 1.0f / l1;
        const size_t row0 = (size_t)(b * SEQ + q0 + rb + mt * 16 + g);
#pragma unroll
        for (int nt = 0; nt < 8; nt++) {
            const int col = h * HD + nt * 8 + 2 * j;
            float2 v0 = make_float2(rna_tf32(o[mt][nt][0] * inv0), rna_tf32(o[mt][nt][1] * inv0));
            float2 v1 = make_float2(rna_tf32(o[mt][nt][2] * inv1), rna_tf32(o[mt][nt][3] * inv1));
            *(float2*)&g_C[row0 * DMODEL + col] = v0;
            *(float2*)&g_C[(row0 + 8) * DMODEL + col] = v1;
        }
    }
}

// ============================================================================
// fused prep: round X | transpose+round weights | concat bias (one launch)
// ============================================================================
#define PREP_X_BLOCKS (MROWS * DMODEL / 256)         // 16384
#define PREP_T_BLOCKS 4096
#define PREP_B_BLOCKS (NQKV / 256)                   // 12

__global__ void prep_all(const float* __restrict__ X,
                         const float* __restrict__ Wq, const float* __restrict__ Wk,
                         const float* __restrict__ Wv, const float* __restrict__ Wo,
                         const float* __restrict__ bq, const float* __restrict__ bk,
                         const float* __restrict__ bv)
{
    const int bid = blockIdx.x;
    const int t = threadIdx.x;
    if (bid < PREP_X_BLOCKS) {
        int i = bid * 256 + t;
        g_A[i] = rna_tf32(X[i]);
    } else if (bid < PREP_X_BLOCKS + PREP_T_BLOCKS) {
        __shared__ float tile[32][33];
        const int r = bid - PREP_X_BLOCKS;
        const int z = r >> 10;
        const int rr = r & 1023;
        const int n0 = (rr & 31) * 32, k0 = (rr >> 5) * 32;
        const float* W = (z == 0) ? Wq : (z == 1) ? Wk : (z == 2) ? Wv : Wo;
        float* Dst = (z == 3) ? g_WtO : (g_WtQKV + (size_t)z * DMODEL * DMODEL);
        const int tx = t & 31, ty0 = t >> 5;
#pragma unroll
        for (int ty = ty0; ty < 32; ty += 8)
            tile[ty][tx] = rna_tf32(W[(size_t)(k0 + ty) * DMODEL + n0 + tx]);
        __syncthreads();
#pragma unroll
        for (int ty = ty0; ty < 32; ty += 8)
            Dst[(size_t)(n0 + ty) * DMODEL + k0 + tx] = tile[tx][ty];
    } else {
        int i = (bid - PREP_X_BLOCKS - PREP_T_BLOCKS) * 256 + t;
        g_biasQKV[i] = (i < 1024) ? bq[i] : (i < 2048) ? bk[i - 1024] : bv[i - 2048];
    }
}

// ============================================================================
extern "C" void kernel_launch(void* const* d_in, const int* in_sizes, int n_in,
                              void* d_out, int out_size)
{
    const float* X    = (const float*)d_in[0];
    const float* mask = (const float*)d_in[1];
    const float* Wq   = (const float*)d_in[2];
    const float* bq   = (const float*)d_in[3];
    const float* Wk   = (const float*)d_in[4];
    const float* bk   = (const float*)d_in[5];
    const float* Wv   = (const float*)d_in[6];
    const float* bv   = (const float*)d_in[7];
    const float* Wo   = (const float*)d_in[8];
    const float* bo   = (const float*)d_in[9];
    float* out = (float*)d_out;

    cudaFuncSetAttribute(gemm_mma, cudaFuncAttributeMaxDynamicSharedMemorySize, GEMM_SMEM);
    cudaFuncSetAttribute(attn_mma, cudaFuncAttributeMaxDynamicSharedMemorySize, ATTN_SMEM);

    float* dA;     cudaGetSymbolAddress((void**)&dA, g_A);
    float* dQKV;   cudaGetSymbolAddress((void**)&dQKV, g_QKV);
    float* dC;     cudaGetSymbolAddress((void**)&dC, g_C);
    float* dWtQKV; cudaGetSymbolAddress((void**)&dWtQKV, g_WtQKV);
    float* dWtO;   cudaGetSymbolAddress((void**)&dWtO, g_WtO);
    float* dBias;  cudaGetSymbolAddress((void**)&dBias, g_biasQKV);

    prep_all<<<PREP_X_BLOCKS + PREP_T_BLOCKS + PREP_B_BLOCKS, 256>>>(
        X, Wq, Wk, Wv, Wo, bq, bk, bv);

    // QKV projection (Q pre-scaled by 0.125*log2e, all tf32-rounded)
    gemm_mma<<<dim3(NQKV / 128, MROWS / 128), 128, GEMM_SMEM>>>(dA, dWtQKV, dBias, dQKV, NQKV, 1);
    // tensor-core flash attention (tensor-core softmax denominator)
    attn_mma<<<dim3(SEQ / ABR, BSZ * NH), 256, ATTN_SMEM>>>(mask);
    // output projection -> d_out
    gemm_mma<<<dim3(DMODEL / 128, MROWS / 128), 128, GEMM_SMEM>>>(dC, dWtO, bo, out, DMODEL, 0);
}